// round 6
// baseline (speedup 1.0000x reference)
#include <cuda_runtime.h>
#include <cstdint>

#define NNODES 50000
#define NEDGES 800000
#define EPSF 1e-7f

// ---------------- static device scratch ----------------
__device__ __align__(16) float g_u0 [NNODES*128];
__device__ __align__(16) float g_v  [NNODES*384];
__device__ __align__(16) float g_bufA[NNODES*384];
__device__ __align__(16) float g_W0hi[128*128];
__device__ __align__(16) float g_W0lo[128*128];
__device__ __align__(16) float g_W1hi[256*128];
__device__ __align__(16) float g_W1lo[256*128];
__device__ __align__(16) float g_W2hi[384*256];
__device__ __align__(16) float g_W2lo[384*256];
__device__ __align__(16) float g_bp0[128];
__device__ __align__(16) float g_bp1[256];
__device__ __align__(16) float g_bp2[384];
__device__ float g_sums[384];
// CSR scratch
__device__ int g_deg[NNODES];
__device__ int g_pos[NNODES];
__device__ int g_rowptr[NNODES + 1];
__device__ int g_srcidx[NEDGES];

// ---------------- helpers ----------------
__device__ __forceinline__ float warpSum(float v){
#pragma unroll
    for (int o = 16; o > 0; o >>= 1) v += __shfl_xor_sync(0xffffffffu, v, o);
    return v;
}
__device__ __forceinline__ float arcosh_cl(float x){
    x = fmaxf(x, 1.0f + EPSF);
    return logf(x + sqrtf(x * x - 1.0f));
}
__device__ __forceinline__ uint32_t tf32r(float x){
    uint32_t r; asm("cvt.rna.tf32.f32 %0, %1;" : "=r"(r) : "f"(x)); return r;
}
__device__ __forceinline__ float tf32f(float x){ return __uint_as_float(tf32r(x)); }

__device__ __forceinline__ void mma_tf32(float* c, const uint32_t* a, uint32_t b0, uint32_t b1){
    asm volatile(
        "mma.sync.aligned.m16n8k8.row.col.f32.tf32.tf32.f32 "
        "{%0,%1,%2,%3}, {%4,%5,%6,%7}, {%8,%9}, {%0,%1,%2,%3};"
        : "+f"(c[0]), "+f"(c[1]), "+f"(c[2]), "+f"(c[3])
        : "r"(a[0]), "r"(a[1]), "r"(a[2]), "r"(a[3]), "r"(b0), "r"(b1));
}
__device__ __forceinline__ uint32_t smem_u32(const void* p){
    return (uint32_t)__cvta_generic_to_shared(p);
}
__device__ __forceinline__ void cp_async16(uint32_t sdst, const void* gsrc, int srcsize){
    asm volatile("cp.async.cg.shared.global [%0], [%1], 16, %2;"
                 :: "r"(sdst), "l"(gsrc), "r"(srcsize) : "memory");
}
#define CP_COMMIT() asm volatile("cp.async.commit_group;" ::: "memory")
#define CP_WAIT(n)  asm volatile("cp.async.wait_group %0;" :: "n"(n) : "memory")

// ---------------- weight padding + tf32 hi/lo split ----------------
template<int MPAD, int KPAD>
__global__ void prep_kernel(const float* __restrict__ W, const float* __restrict__ b,
                            float* __restrict__ Whi, float* __restrict__ Wlo, float* __restrict__ bp){
    int idx = blockIdx.x * blockDim.x + threadIdx.x;
    if (idx < MPAD * KPAD){
        int m = idx / KPAD, k = idx % KPAD;
        float w = (m >= 1 && k >= 1) ? W[(m - 1) * (KPAD - 1) + (k - 1)] : 0.0f;
        float hi = tf32f(w);
        Whi[idx] = hi;
        Wlo[idx] = tf32f(w - hi);
    }
    if (idx < MPAD) bp[idx] = (idx >= 1) ? b[idx - 1] : 0.0f;
}

// ---------------- log_map_zero(x) -> u0 ----------------
__global__ void lmap0_kernel(const float* __restrict__ x){
    int warp = (blockIdx.x * blockDim.x + threadIdx.x) >> 5;
    if (warp >= NNODES) return;
    int lane = threadIdx.x & 31;
    float4 a = ((const float4*)x)[(size_t)warp * 32 + lane];
    float y0 = __shfl_sync(0xffffffffu, a.x, 0);
    float s = a.x*a.x + a.y*a.y + a.z*a.z + a.w*a.w;
    if (lane == 0) s = a.y*a.y + a.z*a.z + a.w*a.w;
    float S = warpSum(s);
    float dist = arcosh_cl(y0 + EPSF);
    float g = dist / sqrtf(S + EPSF);
    float4 u;
    u.x = (lane == 0) ? 0.0f : g * a.x;
    u.y = g * a.y; u.z = g * a.z; u.w = g * a.w;
    ((float4*)g_u0)[(size_t)warp * 32 + lane] = u;
}

// ---------------- CSR build ----------------
__global__ void zero_deg_kernel(){
    int i = blockIdx.x * blockDim.x + threadIdx.x;
    if (i < NNODES) g_deg[i] = 0;
}
__global__ void hist_kernel(const int* __restrict__ ei){
    int e = blockIdx.x * blockDim.x + threadIdx.x;
    if (e < NEDGES) atomicAdd(&g_deg[ei[NEDGES + e]], 1);
}
__global__ void scan_kernel(){   // one block, 1024 threads
    __shared__ int sh[1024];
    int t = threadIdx.x;
    const int PER = (NNODES + 1023) / 1024;   // 49
    int base = t * PER;
    int s = 0;
#pragma unroll 1
    for (int i = 0; i < PER; i++){
        int n = base + i;
        if (n < NNODES) s += g_deg[n];
    }
    sh[t] = s;
    __syncthreads();
    for (int off = 1; off < 1024; off <<= 1){
        int o = (t >= off) ? sh[t - off] : 0;
        __syncthreads();
        sh[t] += o;
        __syncthreads();
    }
    int run = sh[t] - s;   // exclusive
#pragma unroll 1
    for (int i = 0; i < PER; i++){
        int n = base + i;
        if (n < NNODES){
            g_rowptr[n] = run;
            g_pos[n] = run;
            run += g_deg[n];
        }
    }
    if (t == 1023) g_rowptr[NNODES] = run;
}
__global__ void fill_kernel(const int* __restrict__ ei){
    int e = blockIdx.x * blockDim.x + threadIdx.x;
    if (e < NEDGES){
        int dst = ei[NEDGES + e];
        int p = atomicAdd(&g_pos[dst], 1);
        g_srcidx[p] = ei[e];
    }
}

// ---------------- gather (segment_sum) + manpre fused -> bufA (tf32-rounded) ----------------
__global__ void gather_manpre_kernel(){
    int warp = (blockIdx.x * blockDim.x + threadIdx.x) >> 5;
    if (warp >= NNODES) return;
    int lane = threadIdx.x & 31;
    float4 a = ((const float4*)g_u0)[(size_t)warp * 32 + lane];   // self term (1+eps)*xt, eps=0
    int rs = g_rowptr[warp], re = g_rowptr[warp + 1];
    for (int j0 = rs; j0 < re; j0 += 32){
        int myi = j0 + lane;
        int mysrc = (myi < re) ? g_srcidx[myi] : 0;
        int cnt = min(32, re - j0);
        for (int k = 0; k < cnt; k++){
            int src = __shfl_sync(0xffffffffu, mysrc, k);
            float4 v = ((const float4*)g_u0)[(size_t)src * 32 + lane];
            a.x += v.x; a.y += v.y; a.z += v.z; a.w += v.w;
        }
    }
    // col0: u0 col0 = 0 everywhere, so a.x on lane 0 is 0 (matches out[...,0]=0)
    float s = a.x*a.x + a.y*a.y + a.z*a.z + a.w*a.w;
    float S = warpSum(s);
    float n = sqrtf(fmaxf(S + EPSF, 1e-6f));
    float f = sinhf(fminf(n, 50.0f)) / n;
    float fS = f * f * S;
    float first = sqrtf(1.0f + fS);
    float dist = arcosh_cl(first + EPSF);
    float g = dist / sqrtf(fS + EPSF) * f;
    float4 u;
    u.x = tf32f(g*a.x); u.y = tf32f(g*a.y); u.z = tf32f(g*a.z); u.w = tf32f(g*a.w);
    ((float4*)g_bufA)[(size_t)warp * 32 + lane] = u;
}

// ---------------- post-GEMM chain: exp -> log -> relu -> exp -> log (tf32-rounded out) ----------------
template<int MP>
__global__ void rowpost_kernel(const float* __restrict__ V, float* __restrict__ U){
    int warp = (blockIdx.x * blockDim.x + threadIdx.x) >> 5;
    if (warp >= NNODES) return;
    int lane = threadIdx.x & 31;
    constexpr int PL = MP / 128;
    const float4* vr = (const float4*)(V + (size_t)warp * MP);
    float4 a[PL];
    float s = 0.0f;
#pragma unroll
    for (int i = 0; i < PL; i++){
        a[i] = vr[i * 32 + lane];
        s += a[i].x*a[i].x + a[i].y*a[i].y + a[i].z*a[i].z + a[i].w*a[i].w;
    }
    float S = warpSum(s);
    float n = sqrtf(fmaxf(S + EPSF, 1e-6f));
    float f = sinhf(fminf(n, 50.0f)) / n;
    float fS = f * f * S;
    float first = sqrtf(1.0f + fS);
    float dist = arcosh_cl(first + EPSF);
    float g1 = dist / sqrtf(fS + EPSF) * f;
    float s2 = 0.0f;
#pragma unroll
    for (int i = 0; i < PL; i++){
        a[i].x = fmaxf(g1 * a[i].x, 0.0f);
        a[i].y = fmaxf(g1 * a[i].y, 0.0f);
        a[i].z = fmaxf(g1 * a[i].z, 0.0f);
        a[i].w = fmaxf(g1 * a[i].w, 0.0f);
        s2 += a[i].x*a[i].x + a[i].y*a[i].y + a[i].z*a[i].z + a[i].w*a[i].w;
    }
    float S2 = warpSum(s2);
    float n2 = sqrtf(fmaxf(S2 + EPSF, 1e-6f));
    float f2 = sinhf(fminf(n2, 50.0f)) / n2;
    float f2S = f2 * f2 * S2;
    float first2 = sqrtf(1.0f + f2S);
    float dist2 = arcosh_cl(first2 + EPSF);
    float g2 = dist2 / sqrtf(f2S + EPSF) * f2;
    float4* ur = (float4*)(U + (size_t)warp * MP);
#pragma unroll
    for (int i = 0; i < PL; i++){
        float4 o;
        o.x = tf32f(g2*a[i].x); o.y = tf32f(g2*a[i].y);
        o.z = tf32f(g2*a[i].z); o.w = tf32f(g2*a[i].w);
        ur[i * 32 + lane] = o;
    }
}

// ---------------- final rowpost (MP=384) fused with column-mean accumulation ----------------
__global__ void rowpost_final_kernel(const float* __restrict__ V){
    __shared__ float bsum[384];
    int tid = threadIdx.x;
    for (int i = tid; i < 384; i += 256) bsum[i] = 0.0f;
    __syncthreads();
    int warp = (blockIdx.x * blockDim.x + tid) >> 5;
    int lane = tid & 31;
    if (warp < NNODES){
        const float4* vr = (const float4*)(V + (size_t)warp * 384);
        float4 a[3];
        float s = 0.0f;
#pragma unroll
        for (int i = 0; i < 3; i++){
            a[i] = vr[i * 32 + lane];
            s += a[i].x*a[i].x + a[i].y*a[i].y + a[i].z*a[i].z + a[i].w*a[i].w;
        }
        float S = warpSum(s);
        float n = sqrtf(fmaxf(S + EPSF, 1e-6f));
        float f = sinhf(fminf(n, 50.0f)) / n;
        float fS = f * f * S;
        float first = sqrtf(1.0f + fS);
        float dist = arcosh_cl(first + EPSF);
        float g1 = dist / sqrtf(fS + EPSF) * f;
        float s2 = 0.0f;
#pragma unroll
        for (int i = 0; i < 3; i++){
            a[i].x = fmaxf(g1 * a[i].x, 0.0f);
            a[i].y = fmaxf(g1 * a[i].y, 0.0f);
            a[i].z = fmaxf(g1 * a[i].z, 0.0f);
            a[i].w = fmaxf(g1 * a[i].w, 0.0f);
            s2 += a[i].x*a[i].x + a[i].y*a[i].y + a[i].z*a[i].z + a[i].w*a[i].w;
        }
        float S2 = warpSum(s2);
        float n2 = sqrtf(fmaxf(S2 + EPSF, 1e-6f));
        float f2 = sinhf(fminf(n2, 50.0f)) / n2;
        float f2S = f2 * f2 * S2;
        float first2 = sqrtf(1.0f + f2S);
        float dist2 = arcosh_cl(first2 + EPSF);
        float g2 = dist2 / sqrtf(f2S + EPSF) * f2;
#pragma unroll
        for (int i = 0; i < 3; i++){
            int c = i * 128 + lane * 4;
            atomicAdd(&bsum[c + 0], g2 * a[i].x);
            atomicAdd(&bsum[c + 1], g2 * a[i].y);
            atomicAdd(&bsum[c + 2], g2 * a[i].z);
            atomicAdd(&bsum[c + 3], g2 * a[i].w);
        }
    }
    __syncthreads();
    for (int i = tid; i < 384; i += 256) atomicAdd(&g_sums[i], bsum[i]);
}

// ---------------- cp.async double-buffered mma.sync tf32 GEMM ----------------
#define SASTRIDE 36
static constexpr int STG_FLOATS = 3 * 128 * SASTRIDE;
static constexpr int MMA_SMEM = 2 * STG_FLOATS * 4;

template<int K, int MOUT>
__global__ void __launch_bounds__(256, 2) mma_gemm(const float* __restrict__ A,
        const float* __restrict__ Whi, const float* __restrict__ Wlo,
        const float* __restrict__ bias, float* __restrict__ C){
    extern __shared__ float smf[];
    int tid = threadIdx.x, lane = tid & 31, wid = tid >> 5;
    int brow = blockIdx.y * 128, bcol = blockIdx.x * 128;
    int mw = wid & 1, nw = wid >> 1;
    int gid = lane >> 2, tig = lane & 3;
    constexpr int NC = K / 32;

    auto load_stage = [&](int s, int kc){
        float* base = smf + s * STG_FLOATS;
        uint32_t sbA = smem_u32(base);
        uint32_t sbH = smem_u32(base + 128 * SASTRIDE);
        uint32_t sbL = smem_u32(base + 2 * 128 * SASTRIDE);
        int k0 = kc * 32;
#pragma unroll
        for (int i = 0; i < 4; i++){
            int idx = tid + i * 256;
            int r = idx >> 3;
            int c4 = (idx & 7) << 2;
            uint32_t soff = (uint32_t)(r * SASTRIDE + c4) * 4u;
            int gr = brow + r;
            cp_async16(sbA + soff, A + (size_t)gr * K + k0 + c4, (gr < NNODES) ? 16 : 0);
            cp_async16(sbH + soff, Whi + (size_t)(bcol + r) * K + k0 + c4, 16);
            cp_async16(sbL + soff, Wlo + (size_t)(bcol + r) * K + k0 + c4, 16);
        }
        CP_COMMIT();
    };

    float acc[4][4][4];
#pragma unroll
    for (int i = 0; i < 4; i++)
#pragma unroll
        for (int j = 0; j < 4; j++)
#pragma unroll
            for (int l = 0; l < 4; l++) acc[i][j][l] = 0.0f;

    load_stage(0, 0);
    if (NC > 1) load_stage(1, 1);

    for (int kc = 0; kc < NC; kc++){
        int buf = kc & 1;
        if (kc + 1 < NC) { CP_WAIT(1); } else { CP_WAIT(0); }
        __syncthreads();
        const float* sA = smf + buf * STG_FLOATS;
        const float* sH = sA + 128 * SASTRIDE;
        const float* sL = sA + 2 * 128 * SASTRIDE;
#pragma unroll
        for (int ks = 0; ks < 4; ks++){
            int kb = ks * 8;
            uint32_t afr[4][4];
#pragma unroll
            for (int sm2 = 0; sm2 < 4; sm2++){
                int row = mw * 64 + sm2 * 16 + gid;
                afr[sm2][0] = __float_as_uint(sA[row * SASTRIDE + kb + tig]);
                afr[sm2][1] = __float_as_uint(sA[(row + 8) * SASTRIDE + kb + tig]);
                afr[sm2][2] = __float_as_uint(sA[row * SASTRIDE + kb + tig + 4]);
                afr[sm2][3] = __float_as_uint(sA[(row + 8) * SASTRIDE + kb + tig + 4]);
            }
#pragma unroll
            for (int sn = 0; sn < 4; sn++){
                int col = nw * 32 + sn * 8 + gid;
                uint32_t bh0 = __float_as_uint(sH[col * SASTRIDE + kb + tig]);
                uint32_t bh1 = __float_as_uint(sH[col * SASTRIDE + kb + tig + 4]);
                uint32_t bl0 = __float_as_uint(sL[col * SASTRIDE + kb + tig]);
                uint32_t bl1 = __float_as_uint(sL[col * SASTRIDE + kb + tig + 4]);
#pragma unroll
                for (int sm2 = 0; sm2 < 4; sm2++){
                    mma_tf32(acc[sm2][sn], afr[sm2], bh0, bh1);
                    mma_tf32(acc[sm2][sn], afr[sm2], bl0, bl1);
                }
            }
        }
        __syncthreads();
        if (kc + 2 < NC) load_stage(buf, kc + 2);
    }

#pragma unroll
    for (int sm2 = 0; sm2 < 4; sm2++){
#pragma unroll
        for (int sn = 0; sn < 4; sn++){
            int row = brow + mw * 64 + sm2 * 16 + gid;
            int col = bcol + nw * 32 + sn * 8 + tig * 2;
            float2 bb = *(const float2*)(bias + col);
            if (row < NNODES){
                float2 o; o.x = acc[sm2][sn][0] + bb.x; o.y = acc[sm2][sn][1] + bb.y;
                *(float2*)(C + (size_t)row * MOUT + col) = o;
            }
            if (row + 8 < NNODES){
                float2 o; o.x = acc[sm2][sn][2] + bb.x; o.y = acc[sm2][sn][3] + bb.y;
                *(float2*)(C + (size_t)(row + 8) * MOUT + col) = o;
            }
        }
    }
}

// ---------------- mean zero ----------------
__global__ void zero384_kernel(){ g_sums[threadIdx.x] = 0.0f; }

// ---------------- final classifier head ----------------
__global__ void classify_kernel(const float* __restrict__ Wc, const float* __restrict__ bc,
                                float* __restrict__ out){
    __shared__ float sh_hm[384];
    __shared__ float sh_warp[16];
    __shared__ float sh_mx[10];
    __shared__ float sh_factor;
    int t = threadIdx.x, lane = t & 31, wid = t >> 5;
    float v = 0.0f;
    if (t < 384) v = g_sums[t] * (1.0f / (float)NNODES);
    if (t == 0) v = 0.0f;
    if (t < 384) sh_hm[t] = v;
    float s = warpSum(v * v);
    if (lane == 0) sh_warp[wid] = s;
    __syncthreads();
    if (t == 0){
        float S = 0.0f;
        for (int i = 0; i < 16; i++) S += sh_warp[i];
        float nrm = sqrtf(S + EPSF);
        float dist = arcosh_cl(0.0f + EPSF);
        sh_factor = dist / nrm;
    }
    __syncthreads();
    float factor = sh_factor;
    if (wid < 9){
        float d = 0.0f;
        for (int j = lane; j < 383; j += 32) d += sh_hm[j + 1] * factor * Wc[wid * 383 + j];
        d = warpSum(d);
        if (lane == 0) sh_mx[wid + 1] = d + bc[wid];
    }
    if (t == 0) sh_mx[0] = 0.0f;
    __syncthreads();
    if (t == 0){
        float mx[10];
#pragma unroll
        for (int i = 0; i < 10; i++) mx[i] = sh_mx[i];
        float S = 0.0f;
        for (int i = 1; i < 10; i++) S += mx[i] * mx[i];
        float n = sqrtf(fmaxf(S + EPSF, 1e-6f));
        float f = sinhf(fminf(n, 50.0f)) / n;
        float fS = f * f * S;
        float hc[10];
        bool cond = (S == 0.0f);
        if (cond){
            for (int i = 0; i < 10; i++) hc[i] = 0.0f;
        } else {
            hc[0] = sqrtf(1.0f + fS);
            for (int i = 1; i < 10; i++) hc[i] = f * mx[i];
        }
        for (int i = 0; i < 10; i++) out[i] = hc[i];
        float x0c = fmaxf(hc[0] + EPSF, 1.0f + EPSF);
        float dd = logf(x0c + sqrtf(x0c * x0c - 1.0f));
        float tn = 0.0f;
        for (int i = 1; i < 10; i++) tn += hc[i] * hc[i];
        float nr = sqrtf(tn + EPSF);
        float gf = dd / nr;
        float lt[10]; lt[0] = 0.0f;
        for (int i = 1; i < 10; i++) lt[i] = gf * hc[i];
        float mmax = lt[0];
        for (int i = 1; i < 10; i++) mmax = fmaxf(mmax, lt[i]);
        float e[10], se = 0.0f;
        for (int i = 0; i < 10; i++){ e[i] = expf(lt[i] - mmax); se += e[i]; }
        float p[10];
        for (int i = 0; i < 10; i++) p[i] = e[i] / se;
        p[0] = 0.0f;
        float S3 = 0.0f;
        for (int i = 1; i < 10; i++) S3 += p[i] * p[i];
        float n3 = sqrtf(fmaxf(S3 + EPSF, 1e-6f));
        float f3 = sinhf(fminf(n3, 50.0f)) / n3;
        float f3S = f3 * f3 * S3;
        out[10] = sqrtf(1.0f + f3S);
        for (int i = 1; i < 10; i++) out[10 + i] = f3 * p[i];
    }
}

// ---------------- launch ----------------
extern "C" void kernel_launch(void* const* d_in, const int* in_sizes, int n_in,
                              void* d_out, int out_size){
    const float* x  = (const float*)d_in[0];
    const int*   ei = (const int*)  d_in[1];
    const float* W0 = (const float*)d_in[2];
    const float* b0 = (const float*)d_in[3];
    const float* W1 = (const float*)d_in[4];
    const float* b1 = (const float*)d_in[5];
    const float* W2 = (const float*)d_in[6];
    const float* b2 = (const float*)d_in[7];
    const float* Wc = (const float*)d_in[8];
    const float* bc = (const float*)d_in[9];
    float* out = (float*)d_out;

    float *pW0h,*pW0l,*pW1h,*pW1l,*pW2h,*pW2l,*pbp0,*pbp1,*pbp2,*pA,*pV;
    cudaGetSymbolAddress((void**)&pW0h, g_W0hi);
    cudaGetSymbolAddress((void**)&pW0l, g_W0lo);
    cudaGetSymbolAddress((void**)&pW1h, g_W1hi);
    cudaGetSymbolAddress((void**)&pW1l, g_W1lo);
    cudaGetSymbolAddress((void**)&pW2h, g_W2hi);
    cudaGetSymbolAddress((void**)&pW2l, g_W2lo);
    cudaGetSymbolAddress((void**)&pbp0, g_bp0);
    cudaGetSymbolAddress((void**)&pbp1, g_bp1);
    cudaGetSymbolAddress((void**)&pbp2, g_bp2);
    cudaGetSymbolAddress((void**)&pA,   g_bufA);
    cudaGetSymbolAddress((void**)&pV,   g_v);

    cudaFuncSetAttribute(mma_gemm<128,128>, cudaFuncAttributeMaxDynamicSharedMemorySize, MMA_SMEM);
    cudaFuncSetAttribute(mma_gemm<128,256>, cudaFuncAttributeMaxDynamicSharedMemorySize, MMA_SMEM);
    cudaFuncSetAttribute(mma_gemm<256,384>, cudaFuncAttributeMaxDynamicSharedMemorySize, MMA_SMEM);

    prep_kernel<128,128><<<(128*128 + 255)/256, 256>>>(W0, b0, pW0h, pW0l, pbp0);
    prep_kernel<256,128><<<(256*128 + 255)/256, 256>>>(W1, b1, pW1h, pW1l, pbp1);
    prep_kernel<384,256><<<(384*256 + 255)/256, 256>>>(W2, b2, pW2h, pW2l, pbp2);

    const int RB = (NNODES + 7) / 8;
    const int NT = (NNODES + 127) / 128;

    // CSR build (overlaps nothing, but small)
    zero_deg_kernel<<<(NNODES + 255)/256, 256>>>();
    hist_kernel<<<(NEDGES + 255)/256, 256>>>(ei);
    scan_kernel<<<1, 1024>>>();
    fill_kernel<<<(NEDGES + 255)/256, 256>>>(ei);

    lmap0_kernel<<<RB, 256>>>(x);
    gather_manpre_kernel<<<RB, 256>>>();

    mma_gemm<128,128><<<dim3(1, NT), 256, MMA_SMEM>>>(pA, pW0h, pW0l, pbp0, pV);
    rowpost_kernel<128><<<RB, 256>>>(pV, pA);
    mma_gemm<128,256><<<dim3(2, NT), 256, MMA_SMEM>>>(pA, pW1h, pW1l, pbp1, pV);
    rowpost_kernel<256><<<RB, 256>>>(pV, pA);
    mma_gemm<256,384><<<dim3(3, NT), 256, MMA_SMEM>>>(pA, pW2h, pW2l, pbp2, pV);

    zero384_kernel<<<1, 384>>>();
    rowpost_final_kernel<<<RB, 256>>>(pV);
    classify_kernel<<<1, 512>>>(Wc, bc, out);
}

// round 7
// speedup vs baseline: 1.0938x; 1.0938x over previous
#include <cuda_runtime.h>
#include <cstdint>

#define NNODES 50000
#define NEDGES 800000
#define EPSF 1e-7f

// ---------------- static device scratch ----------------
__device__ __align__(16) float g_u0 [NNODES*128];
__device__ __align__(16) float g_acc[NNODES*128];
__device__ __align__(16) float g_v  [NNODES*384];
__device__ __align__(16) float g_bufA[NNODES*384];
__device__ __align__(16) float g_W0hi[128*128];
__device__ __align__(16) float g_W0lo[128*128];
__device__ __align__(16) float g_W1hi[256*128];
__device__ __align__(16) float g_W1lo[256*128];
__device__ __align__(16) float g_W2hi[384*256];
__device__ __align__(16) float g_W2lo[384*256];
__device__ __align__(16) float g_bp0[128];
__device__ __align__(16) float g_bp1[256];
__device__ __align__(16) float g_bp2[384];
__device__ float g_sums[384];

// ---------------- helpers ----------------
__device__ __forceinline__ float warpSum(float v){
#pragma unroll
    for (int o = 16; o > 0; o >>= 1) v += __shfl_xor_sync(0xffffffffu, v, o);
    return v;
}
__device__ __forceinline__ float arcosh_cl(float x){
    x = fmaxf(x, 1.0f + EPSF);
    return logf(x + sqrtf(x * x - 1.0f));
}
__device__ __forceinline__ uint32_t tf32r(float x){
    uint32_t r; asm("cvt.rna.tf32.f32 %0, %1;" : "=r"(r) : "f"(x)); return r;
}
__device__ __forceinline__ float tf32f(float x){ return __uint_as_float(tf32r(x)); }

__device__ __forceinline__ void mma_tf32(float* c, const uint32_t* a, uint32_t b0, uint32_t b1){
    asm volatile(
        "mma.sync.aligned.m16n8k8.row.col.f32.tf32.tf32.f32 "
        "{%0,%1,%2,%3}, {%4,%5,%6,%7}, {%8,%9}, {%0,%1,%2,%3};"
        : "+f"(c[0]), "+f"(c[1]), "+f"(c[2]), "+f"(c[3])
        : "r"(a[0]), "r"(a[1]), "r"(a[2]), "r"(a[3]), "r"(b0), "r"(b1));
}
__device__ __forceinline__ uint32_t smem_u32(const void* p){
    return (uint32_t)__cvta_generic_to_shared(p);
}
__device__ __forceinline__ void cp_async16(uint32_t sdst, const void* gsrc, int srcsize){
    asm volatile("cp.async.cg.shared.global [%0], [%1], 16, %2;"
                 :: "r"(sdst), "l"(gsrc), "r"(srcsize) : "memory");
}
#define CP_COMMIT() asm volatile("cp.async.commit_group;" ::: "memory")
#define CP_WAIT(n)  asm volatile("cp.async.wait_group %0;" :: "n"(n) : "memory")

// ---------------- weight padding + tf32 hi/lo split ----------------
template<int MPAD, int KPAD>
__global__ void prep_kernel(const float* __restrict__ W, const float* __restrict__ b,
                            float* __restrict__ Whi, float* __restrict__ Wlo, float* __restrict__ bp){
    int idx = blockIdx.x * blockDim.x + threadIdx.x;
    if (idx < MPAD * KPAD){
        int m = idx / KPAD, k = idx % KPAD;
        float w = (m >= 1 && k >= 1) ? W[(m - 1) * (KPAD - 1) + (k - 1)] : 0.0f;
        float hi = tf32f(w);
        Whi[idx] = hi;
        Wlo[idx] = tf32f(w - hi);
    }
    if (idx < MPAD) bp[idx] = (idx >= 1) ? b[idx - 1] : 0.0f;
}

// ---------------- log_map_zero(x) -> u0, acc ----------------
__global__ void lmap0_kernel(const float* __restrict__ x){
    int warp = (blockIdx.x * blockDim.x + threadIdx.x) >> 5;
    if (warp >= NNODES) return;
    int lane = threadIdx.x & 31;
    float4 a = ((const float4*)x)[(size_t)warp * 32 + lane];
    float y0 = __shfl_sync(0xffffffffu, a.x, 0);
    float s = a.x*a.x + a.y*a.y + a.z*a.z + a.w*a.w;
    if (lane == 0) s = a.y*a.y + a.z*a.z + a.w*a.w;
    float S = warpSum(s);
    float dist = arcosh_cl(y0 + EPSF);
    float g = dist / sqrtf(S + EPSF);
    float4 u;
    u.x = (lane == 0) ? 0.0f : g * a.x;
    u.y = g * a.y; u.z = g * a.z; u.w = g * a.w;
    ((float4*)g_u0 )[(size_t)warp * 32 + lane] = u;
    ((float4*)g_acc)[(size_t)warp * 32 + lane] = u;
}

// ---------------- segment_sum via vector red.global ----------------
__global__ void scatter_kernel(const int* __restrict__ ei){
    int warp = (blockIdx.x * blockDim.x + threadIdx.x) >> 5;
    if (warp >= NEDGES) return;
    int lane = threadIdx.x & 31;
    int src = ei[warp];
    int dst = ei[NEDGES + warp];
    float4 v = ((const float4*)g_u0)[(size_t)src * 32 + lane];
    float* addr = g_acc + (size_t)dst * 128 + lane * 4;
    asm volatile("red.global.add.v4.f32 [%0], {%1,%2,%3,%4};"
                 :: "l"(addr), "f"(v.x), "f"(v.y), "f"(v.z), "f"(v.w) : "memory");
}

// ---------------- log_map(exp_map(acc)) -> bufA (tf32-rounded) ----------------
__global__ void manpre_kernel(){
    int warp = (blockIdx.x * blockDim.x + threadIdx.x) >> 5;
    if (warp >= NNODES) return;
    int lane = threadIdx.x & 31;
    float4 a = ((const float4*)g_acc)[(size_t)warp * 32 + lane];
    float s = a.x*a.x + a.y*a.y + a.z*a.z + a.w*a.w;
    float S = warpSum(s);
    float n = sqrtf(fmaxf(S + EPSF, 1e-6f));
    float f = sinhf(fminf(n, 50.0f)) / n;
    float fS = f * f * S;
    float first = sqrtf(1.0f + fS);
    float dist = arcosh_cl(first + EPSF);
    float g = dist / sqrtf(fS + EPSF) * f;
    float4 u;
    u.x = tf32f(g*a.x); u.y = tf32f(g*a.y); u.z = tf32f(g*a.z); u.w = tf32f(g*a.w);
    ((float4*)g_bufA)[(size_t)warp * 32 + lane] = u;
}

// ---------------- post-GEMM chain: exp -> log -> relu -> exp -> log (tf32-rounded out) ----------------
template<int MP>
__global__ void rowpost_kernel(const float* __restrict__ V, float* __restrict__ U){
    int warp = (blockIdx.x * blockDim.x + threadIdx.x) >> 5;
    if (warp >= NNODES) return;
    int lane = threadIdx.x & 31;
    constexpr int PL = MP / 128;
    const float4* vr = (const float4*)(V + (size_t)warp * MP);
    float4 a[PL];
    float s = 0.0f;
#pragma unroll
    for (int i = 0; i < PL; i++){
        a[i] = vr[i * 32 + lane];
        s += a[i].x*a[i].x + a[i].y*a[i].y + a[i].z*a[i].z + a[i].w*a[i].w;
    }
    float S = warpSum(s);
    float n = sqrtf(fmaxf(S + EPSF, 1e-6f));
    float f = sinhf(fminf(n, 50.0f)) / n;
    float fS = f * f * S;
    float first = sqrtf(1.0f + fS);
    float dist = arcosh_cl(first + EPSF);
    float g1 = dist / sqrtf(fS + EPSF) * f;
    float s2 = 0.0f;
#pragma unroll
    for (int i = 0; i < PL; i++){
        a[i].x = fmaxf(g1 * a[i].x, 0.0f);
        a[i].y = fmaxf(g1 * a[i].y, 0.0f);
        a[i].z = fmaxf(g1 * a[i].z, 0.0f);
        a[i].w = fmaxf(g1 * a[i].w, 0.0f);
        s2 += a[i].x*a[i].x + a[i].y*a[i].y + a[i].z*a[i].z + a[i].w*a[i].w;
    }
    float S2 = warpSum(s2);
    float n2 = sqrtf(fmaxf(S2 + EPSF, 1e-6f));
    float f2 = sinhf(fminf(n2, 50.0f)) / n2;
    float f2S = f2 * f2 * S2;
    float first2 = sqrtf(1.0f + f2S);
    float dist2 = arcosh_cl(first2 + EPSF);
    float g2 = dist2 / sqrtf(f2S + EPSF) * f2;
    float4* ur = (float4*)(U + (size_t)warp * MP);
#pragma unroll
    for (int i = 0; i < PL; i++){
        float4 o;
        o.x = tf32f(g2*a[i].x); o.y = tf32f(g2*a[i].y);
        o.z = tf32f(g2*a[i].z); o.w = tf32f(g2*a[i].w);
        ur[i * 32 + lane] = o;
    }
}

// ---------------- final rowpost (MP=384) fused with column-mean (contention-free) ----------------
__global__ void rowpost_final_kernel(const float* __restrict__ V){
    __shared__ float sh[8][384];
    int tid = threadIdx.x;
    int wid = tid >> 5, lane = tid & 31;
    int warp = (blockIdx.x * blockDim.x + tid) >> 5;
    if (warp < NNODES){
        const float4* vr = (const float4*)(V + (size_t)warp * 384);
        float4 a[3];
        float s = 0.0f;
#pragma unroll
        for (int i = 0; i < 3; i++){
            a[i] = vr[i * 32 + lane];
            s += a[i].x*a[i].x + a[i].y*a[i].y + a[i].z*a[i].z + a[i].w*a[i].w;
        }
        float S = warpSum(s);
        float n = sqrtf(fmaxf(S + EPSF, 1e-6f));
        float f = sinhf(fminf(n, 50.0f)) / n;
        float fS = f * f * S;
        float first = sqrtf(1.0f + fS);
        float dist = arcosh_cl(first + EPSF);
        float g1 = dist / sqrtf(fS + EPSF) * f;
        float s2 = 0.0f;
#pragma unroll
        for (int i = 0; i < 3; i++){
            a[i].x = fmaxf(g1 * a[i].x, 0.0f);
            a[i].y = fmaxf(g1 * a[i].y, 0.0f);
            a[i].z = fmaxf(g1 * a[i].z, 0.0f);
            a[i].w = fmaxf(g1 * a[i].w, 0.0f);
            s2 += a[i].x*a[i].x + a[i].y*a[i].y + a[i].z*a[i].z + a[i].w*a[i].w;
        }
        float S2 = warpSum(s2);
        float n2 = sqrtf(fmaxf(S2 + EPSF, 1e-6f));
        float f2 = sinhf(fminf(n2, 50.0f)) / n2;
        float f2S = f2 * f2 * S2;
        float first2 = sqrtf(1.0f + f2S);
        float dist2 = arcosh_cl(first2 + EPSF);
        float g2 = dist2 / sqrtf(f2S + EPSF) * f2;
#pragma unroll
        for (int i = 0; i < 3; i++){
            float4 o;
            o.x = g2 * a[i].x; o.y = g2 * a[i].y;
            o.z = g2 * a[i].z; o.w = g2 * a[i].w;
            *(float4*)&sh[wid][i * 128 + lane * 4] = o;
        }
    } else {
#pragma unroll
        for (int i = 0; i < 3; i++)
            *(float4*)&sh[wid][i * 128 + lane * 4] = make_float4(0,0,0,0);
    }
    __syncthreads();
    // reduce 8 warp slices -> global atomic per column
    for (int c = tid; c < 384; c += 256){
        float s = sh[0][c] + sh[1][c] + sh[2][c] + sh[3][c]
                + sh[4][c] + sh[5][c] + sh[6][c] + sh[7][c];
        atomicAdd(&g_sums[c], s);
    }
}

// ---------------- cp.async double-buffered mma.sync tf32 GEMM ----------------
#define SASTRIDE 36
static constexpr int STG_FLOATS = 3 * 128 * SASTRIDE;
static constexpr int MMA_SMEM = 2 * STG_FLOATS * 4;

template<int K, int MOUT>
__global__ void __launch_bounds__(256, 2) mma_gemm(const float* __restrict__ A,
        const float* __restrict__ Whi, const float* __restrict__ Wlo,
        const float* __restrict__ bias, float* __restrict__ C){
    extern __shared__ float smf[];
    int tid = threadIdx.x, lane = tid & 31, wid = tid >> 5;
    int brow = blockIdx.y * 128, bcol = blockIdx.x * 128;
    int mw = wid & 1, nw = wid >> 1;
    int gid = lane >> 2, tig = lane & 3;
    constexpr int NC = K / 32;

    auto load_stage = [&](int s, int kc){
        float* base = smf + s * STG_FLOATS;
        uint32_t sbA = smem_u32(base);
        uint32_t sbH = smem_u32(base + 128 * SASTRIDE);
        uint32_t sbL = smem_u32(base + 2 * 128 * SASTRIDE);
        int k0 = kc * 32;
#pragma unroll
        for (int i = 0; i < 4; i++){
            int idx = tid + i * 256;
            int r = idx >> 3;
            int c4 = (idx & 7) << 2;
            uint32_t soff = (uint32_t)(r * SASTRIDE + c4) * 4u;
            int gr = brow + r;
            cp_async16(sbA + soff, A + (size_t)gr * K + k0 + c4, (gr < NNODES) ? 16 : 0);
            cp_async16(sbH + soff, Whi + (size_t)(bcol + r) * K + k0 + c4, 16);
            cp_async16(sbL + soff, Wlo + (size_t)(bcol + r) * K + k0 + c4, 16);
        }
        CP_COMMIT();
    };

    float acc[4][4][4];
#pragma unroll
    for (int i = 0; i < 4; i++)
#pragma unroll
        for (int j = 0; j < 4; j++)
#pragma unroll
            for (int l = 0; l < 4; l++) acc[i][j][l] = 0.0f;

    load_stage(0, 0);
    if (NC > 1) load_stage(1, 1);

    for (int kc = 0; kc < NC; kc++){
        int buf = kc & 1;
        if (kc + 1 < NC) { CP_WAIT(1); } else { CP_WAIT(0); }
        __syncthreads();
        const float* sA = smf + buf * STG_FLOATS;
        const float* sH = sA + 128 * SASTRIDE;
        const float* sL = sA + 2 * 128 * SASTRIDE;
#pragma unroll
        for (int ks = 0; ks < 4; ks++){
            int kb = ks * 8;
            uint32_t afr[4][4];
#pragma unroll
            for (int sm2 = 0; sm2 < 4; sm2++){
                int row = mw * 64 + sm2 * 16 + gid;
                afr[sm2][0] = __float_as_uint(sA[row * SASTRIDE + kb + tig]);
                afr[sm2][1] = __float_as_uint(sA[(row + 8) * SASTRIDE + kb + tig]);
                afr[sm2][2] = __float_as_uint(sA[row * SASTRIDE + kb + tig + 4]);
                afr[sm2][3] = __float_as_uint(sA[(row + 8) * SASTRIDE + kb + tig + 4]);
            }
#pragma unroll
            for (int sn = 0; sn < 4; sn++){
                int col = nw * 32 + sn * 8 + gid;
                uint32_t bh0 = __float_as_uint(sH[col * SASTRIDE + kb + tig]);
                uint32_t bh1 = __float_as_uint(sH[col * SASTRIDE + kb + tig + 4]);
                uint32_t bl0 = __float_as_uint(sL[col * SASTRIDE + kb + tig]);
                uint32_t bl1 = __float_as_uint(sL[col * SASTRIDE + kb + tig + 4]);
#pragma unroll
                for (int sm2 = 0; sm2 < 4; sm2++){
                    mma_tf32(acc[sm2][sn], afr[sm2], bh0, bh1);
                    mma_tf32(acc[sm2][sn], afr[sm2], bl0, bl1);
                }
            }
        }
        __syncthreads();
        if (kc + 2 < NC) load_stage(buf, kc + 2);
    }

#pragma unroll
    for (int sm2 = 0; sm2 < 4; sm2++){
#pragma unroll
        for (int sn = 0; sn < 4; sn++){
            int row = brow + mw * 64 + sm2 * 16 + gid;
            int col = bcol + nw * 32 + sn * 8 + tig * 2;
            float2 bb = *(const float2*)(bias + col);
            if (row < NNODES){
                float2 o; o.x = acc[sm2][sn][0] + bb.x; o.y = acc[sm2][sn][1] + bb.y;
                *(float2*)(C + (size_t)row * MOUT + col) = o;
            }
            if (row + 8 < NNODES){
                float2 o; o.x = acc[sm2][sn][2] + bb.x; o.y = acc[sm2][sn][3] + bb.y;
                *(float2*)(C + (size_t)(row + 8) * MOUT + col) = o;
            }
        }
    }
}

// ---------------- mean zero ----------------
__global__ void zero384_kernel(){ g_sums[threadIdx.x] = 0.0f; }

// ---------------- final classifier head ----------------
__global__ void classify_kernel(const float* __restrict__ Wc, const float* __restrict__ bc,
                                float* __restrict__ out){
    __shared__ float sh_hm[384];
    __shared__ float sh_warp[16];
    __shared__ float sh_mx[10];
    __shared__ float sh_factor;
    int t = threadIdx.x, lane = t & 31, wid = t >> 5;
    float v = 0.0f;
    if (t < 384) v = g_sums[t] * (1.0f / (float)NNODES);
    if (t == 0) v = 0.0f;
    if (t < 384) sh_hm[t] = v;
    float s = warpSum(v * v);
    if (lane == 0) sh_warp[wid] = s;
    __syncthreads();
    if (t == 0){
        float S = 0.0f;
        for (int i = 0; i < 16; i++) S += sh_warp[i];
        float nrm = sqrtf(S + EPSF);
        float dist = arcosh_cl(0.0f + EPSF);
        sh_factor = dist / nrm;
    }
    __syncthreads();
    float factor = sh_factor;
    if (wid < 9){
        float d = 0.0f;
        for (int j = lane; j < 383; j += 32) d += sh_hm[j + 1] * factor * Wc[wid * 383 + j];
        d = warpSum(d);
        if (lane == 0) sh_mx[wid + 1] = d + bc[wid];
    }
    if (t == 0) sh_mx[0] = 0.0f;
    __syncthreads();
    if (t == 0){
        float mx[10];
#pragma unroll
        for (int i = 0; i < 10; i++) mx[i] = sh_mx[i];
        float S = 0.0f;
        for (int i = 1; i < 10; i++) S += mx[i] * mx[i];
        float n = sqrtf(fmaxf(S + EPSF, 1e-6f));
        float f = sinhf(fminf(n, 50.0f)) / n;
        float fS = f * f * S;
        float hc[10];
        bool cond = (S == 0.0f);
        if (cond){
            for (int i = 0; i < 10; i++) hc[i] = 0.0f;
        } else {
            hc[0] = sqrtf(1.0f + fS);
            for (int i = 1; i < 10; i++) hc[i] = f * mx[i];
        }
        for (int i = 0; i < 10; i++) out[i] = hc[i];
        float x0c = fmaxf(hc[0] + EPSF, 1.0f + EPSF);
        float dd = logf(x0c + sqrtf(x0c * x0c - 1.0f));
        float tn = 0.0f;
        for (int i = 1; i < 10; i++) tn += hc[i] * hc[i];
        float nr = sqrtf(tn + EPSF);
        float gf = dd / nr;
        float lt[10]; lt[0] = 0.0f;
        for (int i = 1; i < 10; i++) lt[i] = gf * hc[i];
        float mmax = lt[0];
        for (int i = 1; i < 10; i++) mmax = fmaxf(mmax, lt[i]);
        float e[10], se = 0.0f;
        for (int i = 0; i < 10; i++){ e[i] = expf(lt[i] - mmax); se += e[i]; }
        float p[10];
        for (int i = 0; i < 10; i++) p[i] = e[i] / se;
        p[0] = 0.0f;
        float S3 = 0.0f;
        for (int i = 1; i < 10; i++) S3 += p[i] * p[i];
        float n3 = sqrtf(fmaxf(S3 + EPSF, 1e-6f));
        float f3 = sinhf(fminf(n3, 50.0f)) / n3;
        float f3S = f3 * f3 * S3;
        out[10] = sqrtf(1.0f + f3S);
        for (int i = 1; i < 10; i++) out[10 + i] = f3 * p[i];
    }
}

// ---------------- launch ----------------
extern "C" void kernel_launch(void* const* d_in, const int* in_sizes, int n_in,
                              void* d_out, int out_size){
    const float* x  = (const float*)d_in[0];
    const int*   ei = (const int*)  d_in[1];
    const float* W0 = (const float*)d_in[2];
    const float* b0 = (const float*)d_in[3];
    const float* W1 = (const float*)d_in[4];
    const float* b1 = (const float*)d_in[5];
    const float* W2 = (const float*)d_in[6];
    const float* b2 = (const float*)d_in[7];
    const float* Wc = (const float*)d_in[8];
    const float* bc = (const float*)d_in[9];
    float* out = (float*)d_out;

    float *pW0h,*pW0l,*pW1h,*pW1l,*pW2h,*pW2l,*pbp0,*pbp1,*pbp2,*pA,*pV;
    cudaGetSymbolAddress((void**)&pW0h, g_W0hi);
    cudaGetSymbolAddress((void**)&pW0l, g_W0lo);
    cudaGetSymbolAddress((void**)&pW1h, g_W1hi);
    cudaGetSymbolAddress((void**)&pW1l, g_W1lo);
    cudaGetSymbolAddress((void**)&pW2h, g_W2hi);
    cudaGetSymbolAddress((void**)&pW2l, g_W2lo);
    cudaGetSymbolAddress((void**)&pbp0, g_bp0);
    cudaGetSymbolAddress((void**)&pbp1, g_bp1);
    cudaGetSymbolAddress((void**)&pbp2, g_bp2);
    cudaGetSymbolAddress((void**)&pA,   g_bufA);
    cudaGetSymbolAddress((void**)&pV,   g_v);

    cudaFuncSetAttribute(mma_gemm<128,128>, cudaFuncAttributeMaxDynamicSharedMemorySize, MMA_SMEM);
    cudaFuncSetAttribute(mma_gemm<128,256>, cudaFuncAttributeMaxDynamicSharedMemorySize, MMA_SMEM);
    cudaFuncSetAttribute(mma_gemm<256,384>, cudaFuncAttributeMaxDynamicSharedMemorySize, MMA_SMEM);

    prep_kernel<128,128><<<(128*128 + 255)/256, 256>>>(W0, b0, pW0h, pW0l, pbp0);
    prep_kernel<256,128><<<(256*128 + 255)/256, 256>>>(W1, b1, pW1h, pW1l, pbp1);
    prep_kernel<384,256><<<(384*256 + 255)/256, 256>>>(W2, b2, pW2h, pW2l, pbp2);

    const int RB = (NNODES + 7) / 8;
    const int NT = (NNODES + 127) / 128;

    lmap0_kernel<<<RB, 256>>>(x);
    scatter_kernel<<<(NEDGES + 7)/8, 256>>>(ei);
    manpre_kernel<<<RB, 256>>>();

    mma_gemm<128,128><<<dim3(1, NT), 256, MMA_SMEM>>>(pA, pW0h, pW0l, pbp0, pV);
    rowpost_kernel<128><<<RB, 256>>>(pV, pA);
    mma_gemm<128,256><<<dim3(2, NT), 256, MMA_SMEM>>>(pA, pW1h, pW1l, pbp1, pV);
    rowpost_kernel<256><<<RB, 256>>>(pV, pA);
    mma_gemm<256,384><<<dim3(3, NT), 256, MMA_SMEM>>>(pA, pW2h, pW2l, pbp2, pV);

    zero384_kernel<<<1, 384>>>();
    rowpost_final_kernel<<<RB, 256>>>(pV);
    classify_kernel<<<1, 512>>>(Wc, bc, out);
}

// round 8
// speedup vs baseline: 1.1365x; 1.0390x over previous
#include <cuda_runtime.h>
#include <cstdint>

#define NNODES 50000
#define NEDGES 800000
#define EPSF 1e-7f

// ---------------- static device scratch ----------------
__device__ __align__(16) float g_u0 [NNODES*128];
__device__ __align__(16) float g_acc[NNODES*128];
__device__ __align__(16) float g_v  [NNODES*384];
__device__ __align__(16) float g_bufA[NNODES*384];
__device__ __align__(16) float g_bufB[NNODES*384];
__device__ __align__(16) float g_W0hi[128*128];
__device__ __align__(16) float g_W0lo[128*128];
__device__ __align__(16) float g_W1hi[256*128];
__device__ __align__(16) float g_W1lo[256*128];
__device__ __align__(16) float g_W2hi[384*256];
__device__ __align__(16) float g_W2lo[384*256];
__device__ __align__(16) float g_bp0[128];
__device__ __align__(16) float g_bp1[256];
__device__ __align__(16) float g_bp2[384];
__device__ float g_sums[384];

// ---------------- helpers ----------------
__device__ __forceinline__ float warpSum(float v){
#pragma unroll
    for (int o = 16; o > 0; o >>= 1) v += __shfl_xor_sync(0xffffffffu, v, o);
    return v;
}
__device__ __forceinline__ float arcosh_cl(float x){
    x = fmaxf(x, 1.0f + EPSF);
    return logf(x + sqrtf(x * x - 1.0f));
}
__device__ __forceinline__ uint32_t tf32r(float x){
    uint32_t r; asm("cvt.rna.tf32.f32 %0, %1;" : "=r"(r) : "f"(x)); return r;
}
__device__ __forceinline__ float tf32f(float x){ return __uint_as_float(tf32r(x)); }

__device__ __forceinline__ void mma_tf32(float* c, const uint32_t* a, uint32_t b0, uint32_t b1){
    asm volatile(
        "mma.sync.aligned.m16n8k8.row.col.f32.tf32.tf32.f32 "
        "{%0,%1,%2,%3}, {%4,%5,%6,%7}, {%8,%9}, {%0,%1,%2,%3};"
        : "+f"(c[0]), "+f"(c[1]), "+f"(c[2]), "+f"(c[3])
        : "r"(a[0]), "r"(a[1]), "r"(a[2]), "r"(a[3]), "r"(b0), "r"(b1));
}
__device__ __forceinline__ uint32_t smem_u32(const void* p){
    return (uint32_t)__cvta_generic_to_shared(p);
}
__device__ __forceinline__ void cp_async16(uint32_t sdst, const void* gsrc, int srcsize){
    asm volatile("cp.async.cg.shared.global [%0], [%1], 16, %2;"
                 :: "r"(sdst), "l"(gsrc), "r"(srcsize) : "memory");
}
#define CP_COMMIT() asm volatile("cp.async.commit_group;" ::: "memory")
#define CP_WAIT(n)  asm volatile("cp.async.wait_group %0;" :: "n"(n) : "memory")

// ---------------- weight padding + tf32 hi/lo split ----------------
template<int MPAD, int KPAD>
__global__ void prep_kernel(const float* __restrict__ W, const float* __restrict__ b,
                            float* __restrict__ Whi, float* __restrict__ Wlo, float* __restrict__ bp){
    int idx = blockIdx.x * blockDim.x + threadIdx.x;
    if (idx < MPAD * KPAD){
        int m = idx / KPAD, k = idx % KPAD;
        float w = (m >= 1 && k >= 1) ? W[(m - 1) * (KPAD - 1) + (k - 1)] : 0.0f;
        float hi = tf32f(w);
        Whi[idx] = hi;
        Wlo[idx] = tf32f(w - hi);
    }
    if (idx < MPAD) bp[idx] = (idx >= 1) ? b[idx - 1] : 0.0f;
}

// ---------------- log_map_zero(x) -> u0, acc ----------------
__global__ void lmap0_kernel(const float* __restrict__ x){
    int warp = (blockIdx.x * blockDim.x + threadIdx.x) >> 5;
    if (warp >= NNODES) return;
    int lane = threadIdx.x & 31;
    float4 a = ((const float4*)x)[(size_t)warp * 32 + lane];
    float y0 = __shfl_sync(0xffffffffu, a.x, 0);
    float s = a.x*a.x + a.y*a.y + a.z*a.z + a.w*a.w;
    if (lane == 0) s = a.y*a.y + a.z*a.z + a.w*a.w;
    float S = warpSum(s);
    float dist = arcosh_cl(y0 + EPSF);
    float g = dist / sqrtf(S + EPSF);
    float4 u;
    u.x = (lane == 0) ? 0.0f : g * a.x;
    u.y = g * a.y; u.z = g * a.z; u.w = g * a.w;
    ((float4*)g_u0 )[(size_t)warp * 32 + lane] = u;
    ((float4*)g_acc)[(size_t)warp * 32 + lane] = u;
}

// ---------------- segment_sum via vector red.global ----------------
__global__ void scatter_kernel(const int* __restrict__ ei){
    int warp = (blockIdx.x * blockDim.x + threadIdx.x) >> 5;
    if (warp >= NEDGES) return;
    int lane = threadIdx.x & 31;
    int src = ei[warp];
    int dst = ei[NEDGES + warp];
    float4 v = ((const float4*)g_u0)[(size_t)src * 32 + lane];
    float* addr = g_acc + (size_t)dst * 128 + lane * 4;
    asm volatile("red.global.add.v4.f32 [%0], {%1,%2,%3,%4};"
                 :: "l"(addr), "f"(v.x), "f"(v.y), "f"(v.z), "f"(v.w) : "memory");
}

// ---------------- log_map(exp_map(acc)) -> bufA (tf32-rounded) ----------------
__global__ void manpre_kernel(){
    int warp = (blockIdx.x * blockDim.x + threadIdx.x) >> 5;
    if (warp >= NNODES) return;
    int lane = threadIdx.x & 31;
    float4 a = ((const float4*)g_acc)[(size_t)warp * 32 + lane];
    float s = a.x*a.x + a.y*a.y + a.z*a.z + a.w*a.w;
    float S = warpSum(s);
    float n = sqrtf(fmaxf(S + EPSF, 1e-6f));
    float f = sinhf(fminf(n, 50.0f)) / n;
    float fS = f * f * S;
    float first = sqrtf(1.0f + fS);
    float dist = arcosh_cl(first + EPSF);
    float g = dist / sqrtf(fS + EPSF) * f;
    float4 u;
    u.x = tf32f(g*a.x); u.y = tf32f(g*a.y); u.z = tf32f(g*a.z); u.w = tf32f(g*a.w);
    ((float4*)g_bufA)[(size_t)warp * 32 + lane] = u;
}

// ---------------- post-GEMM chain: exp -> log -> relu -> exp -> log (tf32-rounded out) ----------------
template<int MP>
__global__ void rowpost_kernel(const float* __restrict__ V, float* __restrict__ U){
    int warp = (blockIdx.x * blockDim.x + threadIdx.x) >> 5;
    if (warp >= NNODES) return;
    int lane = threadIdx.x & 31;
    constexpr int PL = MP / 128;
    const float4* vr = (const float4*)(V + (size_t)warp * MP);
    float4 a[PL];
    float s = 0.0f;
#pragma unroll
    for (int i = 0; i < PL; i++){
        a[i] = vr[i * 32 + lane];
        s += a[i].x*a[i].x + a[i].y*a[i].y + a[i].z*a[i].z + a[i].w*a[i].w;
    }
    float S = warpSum(s);
    float n = sqrtf(fmaxf(S + EPSF, 1e-6f));
    float f = sinhf(fminf(n, 50.0f)) / n;
    float fS = f * f * S;
    float first = sqrtf(1.0f + fS);
    float dist = arcosh_cl(first + EPSF);
    float g1 = dist / sqrtf(fS + EPSF) * f;
    float s2 = 0.0f;
#pragma unroll
    for (int i = 0; i < PL; i++){
        a[i].x = fmaxf(g1 * a[i].x, 0.0f);
        a[i].y = fmaxf(g1 * a[i].y, 0.0f);
        a[i].z = fmaxf(g1 * a[i].z, 0.0f);
        a[i].w = fmaxf(g1 * a[i].w, 0.0f);
        s2 += a[i].x*a[i].x + a[i].y*a[i].y + a[i].z*a[i].z + a[i].w*a[i].w;
    }
    float S2 = warpSum(s2);
    float n2 = sqrtf(fmaxf(S2 + EPSF, 1e-6f));
    float f2 = sinhf(fminf(n2, 50.0f)) / n2;
    float f2S = f2 * f2 * S2;
    float first2 = sqrtf(1.0f + f2S);
    float dist2 = arcosh_cl(first2 + EPSF);
    float g2 = dist2 / sqrtf(f2S + EPSF) * f2;
    float4* ur = (float4*)(U + (size_t)warp * MP);
#pragma unroll
    for (int i = 0; i < PL; i++){
        float4 o;
        o.x = tf32f(g2*a[i].x); o.y = tf32f(g2*a[i].y);
        o.z = tf32f(g2*a[i].z); o.w = tf32f(g2*a[i].w);
        ur[i * 32 + lane] = o;
    }
}

// ---------------- cp.async double-buffered mma.sync tf32 GEMM (256x128 tile) ----------------
// 512 threads = 16 warps (4m x 4n); per-warp tile 64x32; K-chunks of 32.
#define SASTRIDE 36
static constexpr int STG_FLOATS = (256 + 128 + 128) * SASTRIDE;   // 18432 floats
static constexpr int MMA_SMEM = 2 * STG_FLOATS * 4;               // 147456 B

template<int K, int MOUT>
__global__ void __launch_bounds__(512, 1) mma_gemm(const float* __restrict__ A,
        const float* __restrict__ Whi, const float* __restrict__ Wlo,
        const float* __restrict__ bias, float* __restrict__ C){
    extern __shared__ float smf[];
    int tid = threadIdx.x, lane = tid & 31, wid = tid >> 5;
    int brow = blockIdx.y * 256, bcol = blockIdx.x * 128;
    int mw = wid & 3, nw = wid >> 2;
    int gid = lane >> 2, tig = lane & 3;
    constexpr int NC = K / 32;

    auto load_stage = [&](int s, int kc){
        float* base = smf + s * STG_FLOATS;
        uint32_t sbA = smem_u32(base);
        uint32_t sbH = smem_u32(base + 256 * SASTRIDE);
        uint32_t sbL = smem_u32(base + (256 + 128) * SASTRIDE);
        int k0 = kc * 32;
#pragma unroll
        for (int i = 0; i < 4; i++){                 // A: 256 rows x 8 chunks = 2048
            int idx = tid + i * 512;
            int r = idx >> 3;
            int c4 = (idx & 7) << 2;
            int gr = brow + r;
            cp_async16(sbA + (uint32_t)(r * SASTRIDE + c4) * 4u,
                       A + (size_t)gr * K + k0 + c4, (gr < NNODES) ? 16 : 0);
        }
#pragma unroll
        for (int i = 0; i < 2; i++){                 // H,L: 128 rows x 8 chunks = 1024 each
            int idx = tid + i * 512;
            int r = idx >> 3;
            int c4 = (idx & 7) << 2;
            uint32_t soff = (uint32_t)(r * SASTRIDE + c4) * 4u;
            cp_async16(sbH + soff, Whi + (size_t)(bcol + r) * K + k0 + c4, 16);
            cp_async16(sbL + soff, Wlo + (size_t)(bcol + r) * K + k0 + c4, 16);
        }
        CP_COMMIT();
    };

    float acc[4][4][4];
#pragma unroll
    for (int i = 0; i < 4; i++)
#pragma unroll
        for (int j = 0; j < 4; j++)
#pragma unroll
            for (int l = 0; l < 4; l++) acc[i][j][l] = 0.0f;

    load_stage(0, 0);
    if (NC > 1) load_stage(1, 1);

    for (int kc = 0; kc < NC; kc++){
        int buf = kc & 1;
        if (kc + 1 < NC) { CP_WAIT(1); } else { CP_WAIT(0); }
        __syncthreads();
        const float* sA = smf + buf * STG_FLOATS;
        const float* sH = sA + 256 * SASTRIDE;
        const float* sL = sA + (256 + 128) * SASTRIDE;
#pragma unroll
        for (int ks = 0; ks < 4; ks++){
            int kb = ks * 8;
            uint32_t afr[4][4];
#pragma unroll
            for (int sm2 = 0; sm2 < 4; sm2++){
                int row = mw * 64 + sm2 * 16 + gid;
                afr[sm2][0] = __float_as_uint(sA[row * SASTRIDE + kb + tig]);
                afr[sm2][1] = __float_as_uint(sA[(row + 8) * SASTRIDE + kb + tig]);
                afr[sm2][2] = __float_as_uint(sA[row * SASTRIDE + kb + tig + 4]);
                afr[sm2][3] = __float_as_uint(sA[(row + 8) * SASTRIDE + kb + tig + 4]);
            }
#pragma unroll
            for (int sn = 0; sn < 4; sn++){
                int col = nw * 32 + sn * 8 + gid;
                uint32_t bh0 = __float_as_uint(sH[col * SASTRIDE + kb + tig]);
                uint32_t bh1 = __float_as_uint(sH[col * SASTRIDE + kb + tig + 4]);
                uint32_t bl0 = __float_as_uint(sL[col * SASTRIDE + kb + tig]);
                uint32_t bl1 = __float_as_uint(sL[col * SASTRIDE + kb + tig + 4]);
#pragma unroll
                for (int sm2 = 0; sm2 < 4; sm2++){
                    mma_tf32(acc[sm2][sn], afr[sm2], bh0, bh1);
                    mma_tf32(acc[sm2][sn], afr[sm2], bl0, bl1);
                }
            }
        }
        __syncthreads();
        if (kc + 2 < NC) load_stage(buf, kc + 2);
    }

#pragma unroll
    for (int sm2 = 0; sm2 < 4; sm2++){
#pragma unroll
        for (int sn = 0; sn < 4; sn++){
            int row = brow + mw * 64 + sm2 * 16 + gid;
            int col = bcol + nw * 32 + sn * 8 + tig * 2;
            float2 bb = *(const float2*)(bias + col);
            if (row < NNODES){
                float2 o; o.x = acc[sm2][sn][0] + bb.x; o.y = acc[sm2][sn][1] + bb.y;
                *(float2*)(C + (size_t)row * MOUT + col) = o;
            }
            if (row + 8 < NNODES){
                float2 o; o.x = acc[sm2][sn][2] + bb.x; o.y = acc[sm2][sn][3] + bb.y;
                *(float2*)(C + (size_t)(row + 8) * MOUT + col) = o;
            }
        }
    }
}

// ---------------- mean over nodes ----------------
__global__ void zero384_kernel(){ g_sums[threadIdx.x] = 0.0f; }

__global__ void mean_kernel(const float* __restrict__ U){
    int t = threadIdx.x;
    int start = blockIdx.x * 250;
    int end = start + 250;
    float s = 0.0f;
    for (int nn = start; nn < end; nn++) s += U[(size_t)nn * 384 + t];
    atomicAdd(&g_sums[t], s);
}

// ---------------- final classifier head ----------------
__global__ void classify_kernel(const float* __restrict__ Wc, const float* __restrict__ bc,
                                float* __restrict__ out){
    __shared__ float sh_hm[384];
    __shared__ float sh_warp[16];
    __shared__ float sh_mx[10];
    __shared__ float sh_factor;
    int t = threadIdx.x, lane = t & 31, wid = t >> 5;
    float v = 0.0f;
    if (t < 384) v = g_sums[t] * (1.0f / (float)NNODES);
    if (t == 0) v = 0.0f;
    if (t < 384) sh_hm[t] = v;
    float s = warpSum(v * v);
    if (lane == 0) sh_warp[wid] = s;
    __syncthreads();
    if (t == 0){
        float S = 0.0f;
        for (int i = 0; i < 16; i++) S += sh_warp[i];
        float nrm = sqrtf(S + EPSF);
        float dist = arcosh_cl(0.0f + EPSF);
        sh_factor = dist / nrm;
    }
    __syncthreads();
    float factor = sh_factor;
    if (wid < 9){
        float d = 0.0f;
        for (int j = lane; j < 383; j += 32) d += sh_hm[j + 1] * factor * Wc[wid * 383 + j];
        d = warpSum(d);
        if (lane == 0) sh_mx[wid + 1] = d + bc[wid];
    }
    if (t == 0) sh_mx[0] = 0.0f;
    __syncthreads();
    if (t == 0){
        float mx[10];
#pragma unroll
        for (int i = 0; i < 10; i++) mx[i] = sh_mx[i];
        float S = 0.0f;
        for (int i = 1; i < 10; i++) S += mx[i] * mx[i];
        float n = sqrtf(fmaxf(S + EPSF, 1e-6f));
        float f = sinhf(fminf(n, 50.0f)) / n;
        float fS = f * f * S;
        float hc[10];
        bool cond = (S == 0.0f);
        if (cond){
            for (int i = 0; i < 10; i++) hc[i] = 0.0f;
        } else {
            hc[0] = sqrtf(1.0f + fS);
            for (int i = 1; i < 10; i++) hc[i] = f * mx[i];
        }
        for (int i = 0; i < 10; i++) out[i] = hc[i];
        float x0c = fmaxf(hc[0] + EPSF, 1.0f + EPSF);
        float dd = logf(x0c + sqrtf(x0c * x0c - 1.0f));
        float tn = 0.0f;
        for (int i = 1; i < 10; i++) tn += hc[i] * hc[i];
        float nr = sqrtf(tn + EPSF);
        float gf = dd / nr;
        float lt[10]; lt[0] = 0.0f;
        for (int i = 1; i < 10; i++) lt[i] = gf * hc[i];
        float mmax = lt[0];
        for (int i = 1; i < 10; i++) mmax = fmaxf(mmax, lt[i]);
        float e[10], se = 0.0f;
        for (int i = 0; i < 10; i++){ e[i] = expf(lt[i] - mmax); se += e[i]; }
        float p[10];
        for (int i = 0; i < 10; i++) p[i] = e[i] / se;
        p[0] = 0.0f;
        float S3 = 0.0f;
        for (int i = 1; i < 10; i++) S3 += p[i] * p[i];
        float n3 = sqrtf(fmaxf(S3 + EPSF, 1e-6f));
        float f3 = sinhf(fminf(n3, 50.0f)) / n3;
        float f3S = f3 * f3 * S3;
        out[10] = sqrtf(1.0f + f3S);
        for (int i = 1; i < 10; i++) out[10 + i] = f3 * p[i];
    }
}

// ---------------- launch ----------------
extern "C" void kernel_launch(void* const* d_in, const int* in_sizes, int n_in,
                              void* d_out, int out_size){
    const float* x  = (const float*)d_in[0];
    const int*   ei = (const int*)  d_in[1];
    const float* W0 = (const float*)d_in[2];
    const float* b0 = (const float*)d_in[3];
    const float* W1 = (const float*)d_in[4];
    const float* b1 = (const float*)d_in[5];
    const float* W2 = (const float*)d_in[6];
    const float* b2 = (const float*)d_in[7];
    const float* Wc = (const float*)d_in[8];
    const float* bc = (const float*)d_in[9];
    float* out = (float*)d_out;

    float *pW0h,*pW0l,*pW1h,*pW1l,*pW2h,*pW2l,*pbp0,*pbp1,*pbp2,*pA,*pB,*pV;
    cudaGetSymbolAddress((void**)&pW0h, g_W0hi);
    cudaGetSymbolAddress((void**)&pW0l, g_W0lo);
    cudaGetSymbolAddress((void**)&pW1h, g_W1hi);
    cudaGetSymbolAddress((void**)&pW1l, g_W1lo);
    cudaGetSymbolAddress((void**)&pW2h, g_W2hi);
    cudaGetSymbolAddress((void**)&pW2l, g_W2lo);
    cudaGetSymbolAddress((void**)&pbp0, g_bp0);
    cudaGetSymbolAddress((void**)&pbp1, g_bp1);
    cudaGetSymbolAddress((void**)&pbp2, g_bp2);
    cudaGetSymbolAddress((void**)&pA,   g_bufA);
    cudaGetSymbolAddress((void**)&pB,   g_bufB);
    cudaGetSymbolAddress((void**)&pV,   g_v);

    cudaFuncSetAttribute(mma_gemm<128,128>, cudaFuncAttributeMaxDynamicSharedMemorySize, MMA_SMEM);
    cudaFuncSetAttribute(mma_gemm<128,256>, cudaFuncAttributeMaxDynamicSharedMemorySize, MMA_SMEM);
    cudaFuncSetAttribute(mma_gemm<256,384>, cudaFuncAttributeMaxDynamicSharedMemorySize, MMA_SMEM);

    prep_kernel<128,128><<<(128*128 + 255)/256, 256>>>(W0, b0, pW0h, pW0l, pbp0);
    prep_kernel<256,128><<<(256*128 + 255)/256, 256>>>(W1, b1, pW1h, pW1l, pbp1);
    prep_kernel<384,256><<<(384*256 + 255)/256, 256>>>(W2, b2, pW2h, pW2l, pbp2);

    const int RB = (NNODES + 7) / 8;
    const int NT = (NNODES + 255) / 256;   // 196 row tiles

    lmap0_kernel<<<RB, 256>>>(x);
    scatter_kernel<<<(NEDGES + 7)/8, 256>>>(ei);
    manpre_kernel<<<RB, 256>>>();

    mma_gemm<128,128><<<dim3(1, NT), 512, MMA_SMEM>>>(pA, pW0h, pW0l, pbp0, pV);
    rowpost_kernel<128><<<RB, 256>>>(pV, pB);
    mma_gemm<128,256><<<dim3(2, NT), 512, MMA_SMEM>>>(pB, pW1h, pW1l, pbp1, pV);
    rowpost_kernel<256><<<RB, 256>>>(pV, pA);
    mma_gemm<256,384><<<dim3(3, NT), 512, MMA_SMEM>>>(pA, pW2h, pW2l, pbp2, pV);
    rowpost_kernel<384><<<RB, 256>>>(pV, pB);

    zero384_kernel<<<1, 384>>>();
    mean_kernel<<<200, 384>>>(pB);
    classify_kernel<<<1, 512>>>(Wc, bc, out);
}

// round 10
// speedup vs baseline: 1.2529x; 1.1024x over previous
#include <cuda_runtime.h>
#include <cuda_bf16.h>
#include <cstdint>

#define NNODES 50000
#define NEDGES 800000
#define EPSF 1e-7f

// ---------------- static device scratch ----------------
__device__ __align__(16) float g_u0 [NNODES*128];
__device__ __align__(16) float g_acc[NNODES*128];
__device__ __align__(16) float g_v  [NNODES*384];
__device__ __align__(16) float g_bufB[NNODES*384];          // final rowpost fp32 out
__device__ __align__(16) uint32_t g_Ahi[NNODES*128];        // packed bf16x2 planes (max K=256)
__device__ __align__(16) uint32_t g_Alo[NNODES*128];
__device__ __align__(16) uint32_t g_W0hi[128*64];
__device__ __align__(16) uint32_t g_W0lo[128*64];
__device__ __align__(16) uint32_t g_W1hi[256*64];
__device__ __align__(16) uint32_t g_W1lo[256*64];
__device__ __align__(16) uint32_t g_W2hi[384*128];
__device__ __align__(16) uint32_t g_W2lo[384*128];
__device__ __align__(16) float g_bp0[128];
__device__ __align__(16) float g_bp1[256];
__device__ __align__(16) float g_bp2[384];
__device__ float g_sums[384];

// ---------------- helpers ----------------
__device__ __forceinline__ float warpSum(float v){
#pragma unroll
    for (int o = 16; o > 0; o >>= 1) v += __shfl_xor_sync(0xffffffffu, v, o);
    return v;
}
__device__ __forceinline__ float arcosh_cl(float x){
    x = fmaxf(x, 1.0f + EPSF);
    return logf(x + sqrtf(x * x - 1.0f));
}
// bf16 hi/lo split of one float
__device__ __forceinline__ void bfsplit(float x, uint16_t& hi, uint16_t& lo){
    __nv_bfloat16 h = __float2bfloat16_rn(x);
    hi = __bfloat16_as_ushort(h);
    float r = x - __bfloat162float(h);
    lo = __bfloat16_as_ushort(__float2bfloat16_rn(r));
}
// split+pack a float pair (even,odd) into bf16x2 hi and lo words
__device__ __forceinline__ void bfpack2(float x, float y, uint32_t& hi2, uint32_t& lo2){
    uint16_t h0, l0, h1, l1;
    bfsplit(x, h0, l0);
    bfsplit(y, h1, l1);
    hi2 = (uint32_t)h0 | ((uint32_t)h1 << 16);
    lo2 = (uint32_t)l0 | ((uint32_t)l1 << 16);
}
__device__ __forceinline__ void mma_bf16(float* c, const uint32_t* a, uint32_t b0, uint32_t b1){
    asm volatile(
        "mma.sync.aligned.m16n8k16.row.col.f32.bf16.bf16.f32 "
        "{%0,%1,%2,%3}, {%4,%5,%6,%7}, {%8,%9}, {%0,%1,%2,%3};"
        : "+f"(c[0]), "+f"(c[1]), "+f"(c[2]), "+f"(c[3])
        : "r"(a[0]), "r"(a[1]), "r"(a[2]), "r"(a[3]), "r"(b0), "r"(b1));
}
__device__ __forceinline__ uint32_t smem_u32(const void* p){
    return (uint32_t)__cvta_generic_to_shared(p);
}
__device__ __forceinline__ void cp_async16(uint32_t sdst, const void* gsrc, int srcsize){
    asm volatile("cp.async.cg.shared.global [%0], [%1], 16, %2;"
                 :: "r"(sdst), "l"(gsrc), "r"(srcsize) : "memory");
}
#define CP_COMMIT() asm volatile("cp.async.commit_group;" ::: "memory")
#define CP_WAIT(n)  asm volatile("cp.async.wait_group %0;" :: "n"(n) : "memory")

// ---------------- weight padding + bf16 hi/lo split (packed pairs) ----------------
template<int MPAD, int KPAD>
__global__ void prep_kernel(const float* __restrict__ W, const float* __restrict__ b,
                            uint32_t* __restrict__ Whi, uint32_t* __restrict__ Wlo,
                            float* __restrict__ bp){
    int idx = blockIdx.x * blockDim.x + threadIdx.x;
    constexpr int K2 = KPAD / 2;
    if (idx < MPAD * K2){
        int m = idx / K2, kk = idx % K2;
        int k0 = 2 * kk, k1 = 2 * kk + 1;
        float w0 = (m >= 1 && k0 >= 1) ? W[(m - 1) * (KPAD - 1) + (k0 - 1)] : 0.0f;
        float w1 = (m >= 1) ? W[(m - 1) * (KPAD - 1) + (k1 - 1)] : 0.0f;
        uint32_t h2, l2;
        bfpack2(w0, w1, h2, l2);
        Whi[idx] = h2;
        Wlo[idx] = l2;
    }
    if (idx < MPAD) bp[idx] = (idx >= 1) ? b[idx - 1] : 0.0f;
}

// ---------------- log_map_zero(x) -> u0, acc ----------------
__global__ void lmap0_kernel(const float* __restrict__ x){
    int warp = (blockIdx.x * blockDim.x + threadIdx.x) >> 5;
    if (warp >= NNODES) return;
    int lane = threadIdx.x & 31;
    float4 a = ((const float4*)x)[(size_t)warp * 32 + lane];
    float y0 = __shfl_sync(0xffffffffu, a.x, 0);
    float s = a.x*a.x + a.y*a.y + a.z*a.z + a.w*a.w;
    if (lane == 0) s = a.y*a.y + a.z*a.z + a.w*a.w;
    float S = warpSum(s);
    float dist = arcosh_cl(y0 + EPSF);
    float g = dist / sqrtf(S + EPSF);
    float4 u;
    u.x = (lane == 0) ? 0.0f : g * a.x;
    u.y = g * a.y; u.z = g * a.z; u.w = g * a.w;
    ((float4*)g_u0 )[(size_t)warp * 32 + lane] = u;
    ((float4*)g_acc)[(size_t)warp * 32 + lane] = u;
}

// ---------------- segment_sum via vector red.global ----------------
__global__ void scatter_kernel(const int* __restrict__ ei){
    int warp = (blockIdx.x * blockDim.x + threadIdx.x) >> 5;
    if (warp >= NEDGES) return;
    int lane = threadIdx.x & 31;
    int src = ei[warp];
    int dst = ei[NEDGES + warp];
    float4 v = ((const float4*)g_u0)[(size_t)src * 32 + lane];
    float* addr = g_acc + (size_t)dst * 128 + lane * 4;
    asm volatile("red.global.add.v4.f32 [%0], {%1,%2,%3,%4};"
                 :: "l"(addr), "f"(v.x), "f"(v.y), "f"(v.z), "f"(v.w) : "memory");
}

// ---------------- log_map(exp_map(acc)) -> A planes (K=128) ----------------
__global__ void manpre_kernel(){
    int warp = (blockIdx.x * blockDim.x + threadIdx.x) >> 5;
    if (warp >= NNODES) return;
    int lane = threadIdx.x & 31;
    float4 a = ((const float4*)g_acc)[(size_t)warp * 32 + lane];
    float s = a.x*a.x + a.y*a.y + a.z*a.z + a.w*a.w;
    float S = warpSum(s);
    float n = sqrtf(fmaxf(S + EPSF, 1e-6f));
    float f = sinhf(fminf(n, 50.0f)) / n;
    float fS = f * f * S;
    float first = sqrtf(1.0f + fS);
    float dist = arcosh_cl(first + EPSF);
    float g = dist / sqrtf(fS + EPSF) * f;
    uint32_t h0, l0, h1, l1;
    bfpack2(g*a.x, g*a.y, h0, l0);
    bfpack2(g*a.z, g*a.w, h1, l1);
    size_t base = (size_t)warp * 64 + lane * 2;
    g_Ahi[base] = h0; g_Ahi[base + 1] = h1;
    g_Alo[base] = l0; g_Alo[base + 1] = l1;
}

// ---------------- post-GEMM chain -> bf16 planes (intermediate layers) ----------------
template<int MP>
__global__ void rowpost_kernel(const float* __restrict__ V,
                               uint32_t* __restrict__ Uhi, uint32_t* __restrict__ Ulo){
    int warp = (blockIdx.x * blockDim.x + threadIdx.x) >> 5;
    if (warp >= NNODES) return;
    int lane = threadIdx.x & 31;
    constexpr int PL = MP / 128;
    const float4* vr = (const float4*)(V + (size_t)warp * MP);
    float4 a[PL];
    float s = 0.0f;
#pragma unroll
    for (int i = 0; i < PL; i++){
        a[i] = vr[i * 32 + lane];
        s += a[i].x*a[i].x + a[i].y*a[i].y + a[i].z*a[i].z + a[i].w*a[i].w;
    }
    float S = warpSum(s);
    float n = sqrtf(fmaxf(S + EPSF, 1e-6f));
    float f = sinhf(fminf(n, 50.0f)) / n;
    float fS = f * f * S;
    float first = sqrtf(1.0f + fS);
    float dist = arcosh_cl(first + EPSF);
    float g1 = dist / sqrtf(fS + EPSF) * f;
    float s2 = 0.0f;
#pragma unroll
    for (int i = 0; i < PL; i++){
        a[i].x = fmaxf(g1 * a[i].x, 0.0f);
        a[i].y = fmaxf(g1 * a[i].y, 0.0f);
        a[i].z = fmaxf(g1 * a[i].z, 0.0f);
        a[i].w = fmaxf(g1 * a[i].w, 0.0f);
        s2 += a[i].x*a[i].x + a[i].y*a[i].y + a[i].z*a[i].z + a[i].w*a[i].w;
    }
    float S2 = warpSum(s2);
    float n2 = sqrtf(fmaxf(S2 + EPSF, 1e-6f));
    float f2 = sinhf(fminf(n2, 50.0f)) / n2;
    float f2S = f2 * f2 * S2;
    float first2 = sqrtf(1.0f + f2S);
    float dist2 = arcosh_cl(first2 + EPSF);
    float g2 = dist2 / sqrtf(f2S + EPSF) * f2;
#pragma unroll
    for (int i = 0; i < PL; i++){
        uint32_t h0, l0, h1, l1;
        bfpack2(g2*a[i].x, g2*a[i].y, h0, l0);
        bfpack2(g2*a[i].z, g2*a[i].w, h1, l1);
        size_t base = (size_t)warp * (MP / 2) + (size_t)(i * 32 + lane) * 2;
        Uhi[base] = h0; Uhi[base + 1] = h1;
        Ulo[base] = l0; Ulo[base + 1] = l1;
    }
}

// ---------------- final rowpost (MP=384) -> fp32 bufB (feeds mean) ----------------
__global__ void rowpost_final_kernel(const float* __restrict__ V, float* __restrict__ U){
    int warp = (blockIdx.x * blockDim.x + threadIdx.x) >> 5;
    if (warp >= NNODES) return;
    int lane = threadIdx.x & 31;
    const float4* vr = (const float4*)(V + (size_t)warp * 384);
    float4 a[3];
    float s = 0.0f;
#pragma unroll
    for (int i = 0; i < 3; i++){
        a[i] = vr[i * 32 + lane];
        s += a[i].x*a[i].x + a[i].y*a[i].y + a[i].z*a[i].z + a[i].w*a[i].w;
    }
    float S = warpSum(s);
    float n = sqrtf(fmaxf(S + EPSF, 1e-6f));
    float f = sinhf(fminf(n, 50.0f)) / n;
    float fS = f * f * S;
    float first = sqrtf(1.0f + fS);
    float dist = arcosh_cl(first + EPSF);
    float g1 = dist / sqrtf(fS + EPSF) * f;
    float s2 = 0.0f;
#pragma unroll
    for (int i = 0; i < 3; i++){
        a[i].x = fmaxf(g1 * a[i].x, 0.0f);
        a[i].y = fmaxf(g1 * a[i].y, 0.0f);
        a[i].z = fmaxf(g1 * a[i].z, 0.0f);
        a[i].w = fmaxf(g1 * a[i].w, 0.0f);
        s2 += a[i].x*a[i].x + a[i].y*a[i].y + a[i].z*a[i].z + a[i].w*a[i].w;
    }
    float S2 = warpSum(s2);
    float n2 = sqrtf(fmaxf(S2 + EPSF, 1e-6f));
    float f2 = sinhf(fminf(n2, 50.0f)) / n2;
    float f2S = f2 * f2 * S2;
    float first2 = sqrtf(1.0f + f2S);
    float dist2 = arcosh_cl(first2 + EPSF);
    float g2 = dist2 / sqrtf(f2S + EPSF) * f2;
    float4* ur = (float4*)(U + (size_t)warp * 384);
#pragma unroll
    for (int i = 0; i < 3; i++){
        float4 o; o.x = g2*a[i].x; o.y = g2*a[i].y; o.z = g2*a[i].z; o.w = g2*a[i].w;
        ur[i * 32 + lane] = o;
    }
}

// ---------------- cp.async double-buffered bf16 3-MMA GEMM (128x128 tile) ----------------
// A = Ahi + Alo, W = Whi + Wlo (bf16 planes, packed pairs). C = A.W^T + bias (fp32).
// 256 thr (8 warps, 2m x 4n); per-warp 64x32; K-chunks of 32 floats = 16 uint32.
#define ST2 20
static constexpr int STG_U32 = 4 * 128 * ST2;          // Ahi,Alo,Wh,Wl tiles
static constexpr int MMA_SMEM = 2 * STG_U32 * 4;       // 81920 B

template<int K, int MOUT>
__global__ void __launch_bounds__(256, 2) mma_gemm(
        const uint32_t* __restrict__ Ahi, const uint32_t* __restrict__ Alo,
        const uint32_t* __restrict__ Whi, const uint32_t* __restrict__ Wlo,
        const float* __restrict__ bias, float* __restrict__ C){
    extern __shared__ uint32_t smu[];
    int tid = threadIdx.x, lane = tid & 31, wid = tid >> 5;
    int brow = blockIdx.y * 128, bcol = blockIdx.x * 128;
    int mw = wid & 1, nw = wid >> 1;
    int gid = lane >> 2, tig = lane & 3;
    constexpr int NC = K / 32;       // chunks of 32 floats (16 uint32)
    constexpr int K2 = K / 2;        // global row stride in uint32

    auto load_stage = [&](int s, int kc){
        uint32_t* base = smu + s * STG_U32;
        uint32_t sAh = smem_u32(base);
        uint32_t sAl = smem_u32(base + 128 * ST2);
        uint32_t sWh = smem_u32(base + 256 * ST2);
        uint32_t sWl = smem_u32(base + 384 * ST2);
        int k0 = kc * 16;
#pragma unroll
        for (int i = 0; i < 2; i++){
            int idx = tid + i * 256;
            int r = idx >> 2;                  // 0..127
            int c4 = (idx & 3) << 2;           // uint32 offset within chunk (16B units)
            uint32_t soff = (uint32_t)(r * ST2 + c4) * 4u;
            int gr = brow + r;
            int szA = (gr < NNODES) ? 16 : 0;
            cp_async16(sAh + soff, Ahi + (size_t)gr * K2 + k0 + c4, szA);
            cp_async16(sAl + soff, Alo + (size_t)gr * K2 + k0 + c4, szA);
            cp_async16(sWh + soff, Whi + (size_t)(bcol + r) * K2 + k0 + c4, 16);
            cp_async16(sWl + soff, Wlo + (size_t)(bcol + r) * K2 + k0 + c4, 16);
        }
        CP_COMMIT();
    };

    float acc[4][4][4];
#pragma unroll
    for (int i = 0; i < 4; i++)
#pragma unroll
        for (int j = 0; j < 4; j++)
#pragma unroll
            for (int l = 0; l < 4; l++) acc[i][j][l] = 0.0f;

    load_stage(0, 0);
    if (NC > 1) load_stage(1, 1);

    for (int kc = 0; kc < NC; kc++){
        int buf = kc & 1;
        if (kc + 1 < NC) { CP_WAIT(1); } else { CP_WAIT(0); }
        __syncthreads();
        const uint32_t* sAh = smu + buf * STG_U32;
        const uint32_t* sAl = sAh + 128 * ST2;
        const uint32_t* sWh = sAh + 256 * ST2;
        const uint32_t* sWl = sAh + 384 * ST2;
#pragma unroll
        for (int ks = 0; ks < 2; ks++){        // two K=16 steps per 32-float chunk
            int kb = ks * 8;                   // uint32 offset
            uint32_t ah[4][4], al[4][4];
#pragma unroll
            for (int sm2 = 0; sm2 < 4; sm2++){
                int row = mw * 64 + sm2 * 16 + gid;
                int r0 = row * ST2 + kb + tig;
                int r1 = (row + 8) * ST2 + kb + tig;
                ah[sm2][0] = sAh[r0]; ah[sm2][1] = sAh[r1];
                ah[sm2][2] = sAh[r0 + 4]; ah[sm2][3] = sAh[r1 + 4];
                al[sm2][0] = sAl[r0]; al[sm2][1] = sAl[r1];
                al[sm2][2] = sAl[r0 + 4]; al[sm2][3] = sAl[r1 + 4];
            }
#pragma unroll
            for (int sn = 0; sn < 4; sn++){
                int col = nw * 32 + sn * 8 + gid;
                int c0 = col * ST2 + kb + tig;
                uint32_t wh0 = sWh[c0], wh1 = sWh[c0 + 4];
                uint32_t wl0 = sWl[c0], wl1 = sWl[c0 + 4];
#pragma unroll
                for (int sm2 = 0; sm2 < 4; sm2++){
                    mma_bf16(acc[sm2][sn], ah[sm2], wh0, wh1);
                    mma_bf16(acc[sm2][sn], ah[sm2], wl0, wl1);
                    mma_bf16(acc[sm2][sn], al[sm2], wh0, wh1);
                }
            }
        }
        __syncthreads();
        if (kc + 2 < NC) load_stage(buf, kc + 2);
    }

#pragma unroll
    for (int sm2 = 0; sm2 < 4; sm2++){
#pragma unroll
        for (int sn = 0; sn < 4; sn++){
            int row = brow + mw * 64 + sm2 * 16 + gid;
            int col = bcol + nw * 32 + sn * 8 + tig * 2;
            float2 bb = *(const float2*)(bias + col);
            if (row < NNODES){
                float2 o; o.x = acc[sm2][sn][0] + bb.x; o.y = acc[sm2][sn][1] + bb.y;
                *(float2*)(C + (size_t)row * MOUT + col) = o;
            }
            if (row + 8 < NNODES){
                float2 o; o.x = acc[sm2][sn][2] + bb.x; o.y = acc[sm2][sn][3] + bb.y;
                *(float2*)(C + (size_t)(row + 8) * MOUT + col) = o;
            }
        }
    }
}

// ---------------- mean over nodes ----------------
__global__ void zero384_kernel(){ g_sums[threadIdx.x] = 0.0f; }

__global__ void mean_kernel(const float* __restrict__ U){
    int t = threadIdx.x;
    int start = blockIdx.x * 250;
    int end = start + 250;
    float s = 0.0f;
    for (int nn = start; nn < end; nn++) s += U[(size_t)nn * 384 + t];
    atomicAdd(&g_sums[t], s);
}

// ---------------- final classifier head ----------------
__global__ void classify_kernel(const float* __restrict__ Wc, const float* __restrict__ bc,
                                float* __restrict__ out){
    __shared__ float sh_hm[384];
    __shared__ float sh_warp[16];
    __shared__ float sh_mx[10];
    __shared__ float sh_factor;
    int t = threadIdx.x, lane = t & 31, wid = t >> 5;
    float v = 0.0f;
    if (t < 384) v = g_sums[t] * (1.0f / (float)NNODES);
    if (t == 0) v = 0.0f;
    if (t < 384) sh_hm[t] = v;
    float s = warpSum(v * v);
    if (lane == 0) sh_warp[wid] = s;
    __syncthreads();
    if (t == 0){
        float S = 0.0f;
        for (int i = 0; i < 16; i++) S += sh_warp[i];
        float nrm = sqrtf(S + EPSF);
        float dist = arcosh_cl(0.0f + EPSF);
        sh_factor = dist / nrm;
    }
    __syncthreads();
    float factor = sh_factor;
    if (wid < 9){
        float d = 0.0f;
        for (int j = lane; j < 383; j += 32) d += sh_hm[j + 1] * factor * Wc[wid * 383 + j];
        d = warpSum(d);
        if (lane == 0) sh_mx[wid + 1] = d + bc[wid];
    }
    if (t == 0) sh_mx[0] = 0.0f;
    __syncthreads();
    if (t == 0){
        float mx[10];
#pragma unroll
        for (int i = 0; i < 10; i++) mx[i] = sh_mx[i];
        float S = 0.0f;
        for (int i = 1; i < 10; i++) S += mx[i] * mx[i];
        float n = sqrtf(fmaxf(S + EPSF, 1e-6f));
        float f = sinhf(fminf(n, 50.0f)) / n;
        float fS = f * f * S;
        float hc[10];
        bool cond = (S == 0.0f);
        if (cond){
            for (int i = 0; i < 10; i++) hc[i] = 0.0f;
        } else {
            hc[0] = sqrtf(1.0f + fS);
            for (int i = 1; i < 10; i++) hc[i] = f * mx[i];
        }
        for (int i = 0; i < 10; i++) out[i] = hc[i];
        float x0c = fmaxf(hc[0] + EPSF, 1.0f + EPSF);
        float dd = logf(x0c + sqrtf(x0c * x0c - 1.0f));
        float tn = 0.0f;
        for (int i = 1; i < 10; i++) tn += hc[i] * hc[i];
        float nr = sqrtf(tn + EPSF);
        float gf = dd / nr;
        float lt[10]; lt[0] = 0.0f;
        for (int i = 1; i < 10; i++) lt[i] = gf * hc[i];
        float mmax = lt[0];
        for (int i = 1; i < 10; i++) mmax = fmaxf(mmax, lt[i]);
        float e[10], se = 0.0f;
        for (int i = 0; i < 10; i++){ e[i] = expf(lt[i] - mmax); se += e[i]; }
        float p[10];
        for (int i = 0; i < 10; i++) p[i] = e[i] / se;
        p[0] = 0.0f;
        float S3 = 0.0f;
        for (int i = 1; i < 10; i++) S3 += p[i] * p[i];
        float n3 = sqrtf(fmaxf(S3 + EPSF, 1e-6f));
        float f3 = sinhf(fminf(n3, 50.0f)) / n3;
        float f3S = f3 * f3 * S3;
        out[10] = sqrtf(1.0f + f3S);
        for (int i = 1; i < 10; i++) out[10 + i] = f3 * p[i];
    }
}

// ---------------- launch ----------------
extern "C" void kernel_launch(void* const* d_in, const int* in_sizes, int n_in,
                              void* d_out, int out_size){
    const float* x  = (const float*)d_in[0];
    const int*   ei = (const int*)  d_in[1];
    const float* W0 = (const float*)d_in[2];
    const float* b0 = (const float*)d_in[3];
    const float* W1 = (const float*)d_in[4];
    const float* b1 = (const float*)d_in[5];
    const float* W2 = (const float*)d_in[6];
    const float* b2 = (const float*)d_in[7];
    const float* Wc = (const float*)d_in[8];
    const float* bc = (const float*)d_in[9];
    float* out = (float*)d_out;

    uint32_t *pW0h,*pW0l,*pW1h,*pW1l,*pW2h,*pW2l,*pAh,*pAl;
    float *pbp0,*pbp1,*pbp2,*pB,*pV;
    cudaGetSymbolAddress((void**)&pW0h, g_W0hi);
    cudaGetSymbolAddress((void**)&pW0l, g_W0lo);
    cudaGetSymbolAddress((void**)&pW1h, g_W1hi);
    cudaGetSymbolAddress((void**)&pW1l, g_W1lo);
    cudaGetSymbolAddress((void**)&pW2h, g_W2hi);
    cudaGetSymbolAddress((void**)&pW2l, g_W2lo);
    cudaGetSymbolAddress((void**)&pbp0, g_bp0);
    cudaGetSymbolAddress((void**)&pbp1, g_bp1);
    cudaGetSymbolAddress((void**)&pbp2, g_bp2);
    cudaGetSymbolAddress((void**)&pAh,  g_Ahi);
    cudaGetSymbolAddress((void**)&pAl,  g_Alo);
    cudaGetSymbolAddress((void**)&pB,   g_bufB);
    cudaGetSymbolAddress((void**)&pV,   g_v);

    cudaFuncSetAttribute(mma_gemm<128,128>, cudaFuncAttributeMaxDynamicSharedMemorySize, MMA_SMEM);
    cudaFuncSetAttribute(mma_gemm<128,256>, cudaFuncAttributeMaxDynamicSharedMemorySize, MMA_SMEM);
    cudaFuncSetAttribute(mma_gemm<256,384>, cudaFuncAttributeMaxDynamicSharedMemorySize, MMA_SMEM);

    prep_kernel<128,128><<<(128*64 + 255)/256, 256>>>(W0, b0, pW0h, pW0l, pbp0);
    prep_kernel<256,128><<<(256*64 + 255)/256, 256>>>(W1, b1, pW1h, pW1l, pbp1);
    prep_kernel<384,256><<<(384*128 + 255)/256, 256>>>(W2, b2, pW2h, pW2l, pbp2);

    const int RB = (NNODES + 7) / 8;
    const int NT = (NNODES + 127) / 128;   // 391 row tiles

    lmap0_kernel<<<RB, 256>>>(x);
    scatter_kernel<<<(NEDGES + 7)/8, 256>>>(ei);
    manpre_kernel<<<RB, 256>>>();

    mma_gemm<128,128><<<dim3(1, NT), 256, MMA_SMEM>>>(pAh, pAl, pW0h, pW0l, pbp0, pV);
    rowpost_kernel<128><<<RB, 256>>>(pV, pAh, pAl);
    mma_gemm<128,256><<<dim3(2, NT), 256, MMA_SMEM>>>(pAh, pAl, pW1h, pW1l, pbp1, pV);
    rowpost_kernel<256><<<RB, 256>>>(pV, pAh, pAl);
    mma_gemm<256,384><<<dim3(3, NT), 256, MMA_SMEM>>>(pAh, pAl, pW2h, pW2l, pbp2, pV);
    rowpost_final_kernel<<<RB, 256>>>(pV, pB);

    zero384_kernel<<<1, 384>>>();
    mean_kernel<<<200, 384>>>(pB);
    classify_kernel<<<1, 512>>>(Wc, bc, out);
}

// round 11
// speedup vs baseline: 1.4380x; 1.1477x over previous
#include <cuda_runtime.h>
#include <cuda_bf16.h>
#include <cstdint>

#define NNODES 50000
#define NEDGES 800000
#define EPSF 1e-7f

// ---------------- static device scratch ----------------
__device__ __align__(16) float g_u0 [NNODES*128];
__device__ __align__(16) float g_acc[NNODES*128];
__device__ __align__(16) float g_v  [NNODES*384];
__device__ __align__(16) float g_bufB[NNODES*384];          // final rowpost fp32 out
__device__ __align__(16) uint32_t g_Ahi[NNODES*128];        // packed bf16x2 A (max K=256)
__device__ __align__(16) uint32_t g_W0hi[128*64];
__device__ __align__(16) uint32_t g_W0lo[128*64];
__device__ __align__(16) uint32_t g_W1hi[256*64];
__device__ __align__(16) uint32_t g_W1lo[256*64];
__device__ __align__(16) uint32_t g_W2hi[384*128];
__device__ __align__(16) uint32_t g_W2lo[384*128];
__device__ __align__(16) float g_bp0[128];
__device__ __align__(16) float g_bp1[256];
__device__ __align__(16) float g_bp2[384];
__device__ float g_sums[384];

// ---------------- helpers ----------------
__device__ __forceinline__ float warpSum(float v){
#pragma unroll
    for (int o = 16; o > 0; o >>= 1) v += __shfl_xor_sync(0xffffffffu, v, o);
    return v;
}
__device__ __forceinline__ float arcosh_cl(float x){
    x = fmaxf(x, 1.0f + EPSF);
    return logf(x + sqrtf(x * x - 1.0f));
}
// bf16 hi/lo split of one float
__device__ __forceinline__ void bfsplit(float x, uint16_t& hi, uint16_t& lo){
    __nv_bfloat16 h = __float2bfloat16_rn(x);
    hi = __bfloat16_as_ushort(h);
    float r = x - __bfloat162float(h);
    lo = __bfloat16_as_ushort(__float2bfloat16_rn(r));
}
// split+pack a float pair into bf16x2 hi and lo words
__device__ __forceinline__ void bfpack2(float x, float y, uint32_t& hi2, uint32_t& lo2){
    uint16_t h0, l0, h1, l1;
    bfsplit(x, h0, l0);
    bfsplit(y, h1, l1);
    hi2 = (uint32_t)h0 | ((uint32_t)h1 << 16);
    lo2 = (uint32_t)l0 | ((uint32_t)l1 << 16);
}
// plain pack of a float pair into bf16x2 (round-to-nearest)
__device__ __forceinline__ uint32_t bfpack2hi(float x, float y){
    uint16_t h0 = __bfloat16_as_ushort(__float2bfloat16_rn(x));
    uint16_t h1 = __bfloat16_as_ushort(__float2bfloat16_rn(y));
    return (uint32_t)h0 | ((uint32_t)h1 << 16);
}
__device__ __forceinline__ void mma_bf16(float* c, const uint32_t* a, uint32_t b0, uint32_t b1){
    asm volatile(
        "mma.sync.aligned.m16n8k16.row.col.f32.bf16.bf16.f32 "
        "{%0,%1,%2,%3}, {%4,%5,%6,%7}, {%8,%9}, {%0,%1,%2,%3};"
        : "+f"(c[0]), "+f"(c[1]), "+f"(c[2]), "+f"(c[3])
        : "r"(a[0]), "r"(a[1]), "r"(a[2]), "r"(a[3]), "r"(b0), "r"(b1));
}
__device__ __forceinline__ uint32_t smem_u32(const void* p){
    return (uint32_t)__cvta_generic_to_shared(p);
}
__device__ __forceinline__ void cp_async16(uint32_t sdst, const void* gsrc, int srcsize){
    asm volatile("cp.async.cg.shared.global [%0], [%1], 16, %2;"
                 :: "r"(sdst), "l"(gsrc), "r"(srcsize) : "memory");
}
#define CP_COMMIT() asm volatile("cp.async.commit_group;" ::: "memory")
#define CP_WAIT(n)  asm volatile("cp.async.wait_group %0;" :: "n"(n) : "memory")

// ---------------- weight padding + bf16 hi/lo split (packed pairs) ----------------
template<int MPAD, int KPAD>
__global__ void prep_kernel(const float* __restrict__ W, const float* __restrict__ b,
                            uint32_t* __restrict__ Whi, uint32_t* __restrict__ Wlo,
                            float* __restrict__ bp){
    int idx = blockIdx.x * blockDim.x + threadIdx.x;
    constexpr int K2 = KPAD / 2;
    if (idx < MPAD * K2){
        int m = idx / K2, kk = idx % K2;
        int k0 = 2 * kk, k1 = 2 * kk + 1;
        float w0 = (m >= 1 && k0 >= 1) ? W[(m - 1) * (KPAD - 1) + (k0 - 1)] : 0.0f;
        float w1 = (m >= 1) ? W[(m - 1) * (KPAD - 1) + (k1 - 1)] : 0.0f;
        uint32_t h2, l2;
        bfpack2(w0, w1, h2, l2);
        Whi[idx] = h2;
        Wlo[idx] = l2;
    }
    if (idx < MPAD) bp[idx] = (idx >= 1) ? b[idx - 1] : 0.0f;
}

// ---------------- log_map_zero(x) -> u0, acc ----------------
__global__ void lmap0_kernel(const float* __restrict__ x){
    int warp = (blockIdx.x * blockDim.x + threadIdx.x) >> 5;
    if (warp >= NNODES) return;
    int lane = threadIdx.x & 31;
    float4 a = ((const float4*)x)[(size_t)warp * 32 + lane];
    float y0 = __shfl_sync(0xffffffffu, a.x, 0);
    float s = a.x*a.x + a.y*a.y + a.z*a.z + a.w*a.w;
    if (lane == 0) s = a.y*a.y + a.z*a.z + a.w*a.w;
    float S = warpSum(s);
    float dist = arcosh_cl(y0 + EPSF);
    float g = dist / sqrtf(S + EPSF);
    float4 u;
    u.x = (lane == 0) ? 0.0f : g * a.x;
    u.y = g * a.y; u.z = g * a.z; u.w = g * a.w;
    ((float4*)g_u0 )[(size_t)warp * 32 + lane] = u;
    ((float4*)g_acc)[(size_t)warp * 32 + lane] = u;
}

// ---------------- segment_sum via vector red.global ----------------
__global__ void scatter_kernel(const int* __restrict__ ei){
    int warp = (blockIdx.x * blockDim.x + threadIdx.x) >> 5;
    if (warp >= NEDGES) return;
    int lane = threadIdx.x & 31;
    int src = ei[warp];
    int dst = ei[NEDGES + warp];
    float4 v = ((const float4*)g_u0)[(size_t)src * 32 + lane];
    float* addr = g_acc + (size_t)dst * 128 + lane * 4;
    asm volatile("red.global.add.v4.f32 [%0], {%1,%2,%3,%4};"
                 :: "l"(addr), "f"(v.x), "f"(v.y), "f"(v.z), "f"(v.w) : "memory");
}

// ---------------- log_map(exp_map(acc)) -> A plane (K=128) ----------------
__global__ void manpre_kernel(){
    int warp = (blockIdx.x * blockDim.x + threadIdx.x) >> 5;
    if (warp >= NNODES) return;
    int lane = threadIdx.x & 31;
    float4 a = ((const float4*)g_acc)[(size_t)warp * 32 + lane];
    float s = a.x*a.x + a.y*a.y + a.z*a.z + a.w*a.w;
    float S = warpSum(s);
    float n = sqrtf(fmaxf(S + EPSF, 1e-6f));
    float f = sinhf(fminf(n, 50.0f)) / n;
    float fS = f * f * S;
    float first = sqrtf(1.0f + fS);
    float dist = arcosh_cl(first + EPSF);
    float g = dist / sqrtf(fS + EPSF) * f;
    uint2 h;
    h.x = bfpack2hi(g*a.x, g*a.y);
    h.y = bfpack2hi(g*a.z, g*a.w);
    ((uint2*)g_Ahi)[(size_t)warp * 32 + lane] = h;
}

// ---------------- post-GEMM chain -> bf16 A plane (intermediate layers) ----------------
template<int MP>
__global__ void rowpost_kernel(const float* __restrict__ V, uint32_t* __restrict__ Uhi){
    int warp = (blockIdx.x * blockDim.x + threadIdx.x) >> 5;
    if (warp >= NNODES) return;
    int lane = threadIdx.x & 31;
    constexpr int PL = MP / 128;
    const float4* vr = (const float4*)(V + (size_t)warp * MP);
    float4 a[PL];
    float s = 0.0f;
#pragma unroll
    for (int i = 0; i < PL; i++){
        a[i] = vr[i * 32 + lane];
        s += a[i].x*a[i].x + a[i].y*a[i].y + a[i].z*a[i].z + a[i].w*a[i].w;
    }
    float S = warpSum(s);
    float n = sqrtf(fmaxf(S + EPSF, 1e-6f));
    float f = sinhf(fminf(n, 50.0f)) / n;
    float fS = f * f * S;
    float first = sqrtf(1.0f + fS);
    float dist = arcosh_cl(first + EPSF);
    float g1 = dist / sqrtf(fS + EPSF) * f;
    float s2 = 0.0f;
#pragma unroll
    for (int i = 0; i < PL; i++){
        a[i].x = fmaxf(g1 * a[i].x, 0.0f);
        a[i].y = fmaxf(g1 * a[i].y, 0.0f);
        a[i].z = fmaxf(g1 * a[i].z, 0.0f);
        a[i].w = fmaxf(g1 * a[i].w, 0.0f);
        s2 += a[i].x*a[i].x + a[i].y*a[i].y + a[i].z*a[i].z + a[i].w*a[i].w;
    }
    float S2 = warpSum(s2);
    float n2 = sqrtf(fmaxf(S2 + EPSF, 1e-6f));
    float f2 = sinhf(fminf(n2, 50.0f)) / n2;
    float f2S = f2 * f2 * S2;
    float first2 = sqrtf(1.0f + f2S);
    float dist2 = arcosh_cl(first2 + EPSF);
    float g2 = dist2 / sqrtf(f2S + EPSF) * f2;
#pragma unroll
    for (int i = 0; i < PL; i++){
        uint2 h;
        h.x = bfpack2hi(g2*a[i].x, g2*a[i].y);
        h.y = bfpack2hi(g2*a[i].z, g2*a[i].w);
        ((uint2*)Uhi)[(size_t)warp * (MP / 4) + i * 32 + lane] = h;
    }
}

// ---------------- final rowpost (MP=384) -> fp32 bufB (feeds mean) ----------------
__global__ void rowpost_final_kernel(const float* __restrict__ V, float* __restrict__ U){
    int warp = (blockIdx.x * blockDim.x + threadIdx.x) >> 5;
    if (warp >= NNODES) return;
    int lane = threadIdx.x & 31;
    const float4* vr = (const float4*)(V + (size_t)warp * 384);
    float4 a[3];
    float s = 0.0f;
#pragma unroll
    for (int i = 0; i < 3; i++){
        a[i] = vr[i * 32 + lane];
        s += a[i].x*a[i].x + a[i].y*a[i].y + a[i].z*a[i].z + a[i].w*a[i].w;
    }
    float S = warpSum(s);
    float n = sqrtf(fmaxf(S + EPSF, 1e-6f));
    float f = sinhf(fminf(n, 50.0f)) / n;
    float fS = f * f * S;
    float first = sqrtf(1.0f + fS);
    float dist = arcosh_cl(first + EPSF);
    float g1 = dist / sqrtf(fS + EPSF) * f;
    float s2 = 0.0f;
#pragma unroll
    for (int i = 0; i < 3; i++){
        a[i].x = fmaxf(g1 * a[i].x, 0.0f);
        a[i].y = fmaxf(g1 * a[i].y, 0.0f);
        a[i].z = fmaxf(g1 * a[i].z, 0.0f);
        a[i].w = fmaxf(g1 * a[i].w, 0.0f);
        s2 += a[i].x*a[i].x + a[i].y*a[i].y + a[i].z*a[i].z + a[i].w*a[i].w;
    }
    float S2 = warpSum(s2);
    float n2 = sqrtf(fmaxf(S2 + EPSF, 1e-6f));
    float f2 = sinhf(fminf(n2, 50.0f)) / n2;
    float f2S = f2 * f2 * S2;
    float first2 = sqrtf(1.0f + f2S);
    float dist2 = arcosh_cl(first2 + EPSF);
    float g2 = dist2 / sqrtf(f2S + EPSF) * f2;
    float4* ur = (float4*)(U + (size_t)warp * 384);
#pragma unroll
    for (int i = 0; i < 3; i++){
        float4 o; o.x = g2*a[i].x; o.y = g2*a[i].y; o.z = g2*a[i].z; o.w = g2*a[i].w;
        ur[i * 32 + lane] = o;
    }
}

// ---------------- cp.async double-buffered bf16 2-MMA GEMM (128x128 tile) ----------------
// A bf16, W = Whi + Wlo. C = A.W^T + bias (fp32).
// 256 thr (8 warps, 2m x 4n); per-warp 64x32; K-chunks of 32 floats = 16 uint32.
#define ST2 20
static constexpr int STG_U32 = 3 * 128 * ST2;          // Ah,Wh,Wl tiles
static constexpr int MMA_SMEM = 2 * STG_U32 * 4;       // 61440 B

template<int K, int MOUT>
__global__ void __launch_bounds__(256, 2) mma_gemm(
        const uint32_t* __restrict__ Ahi,
        const uint32_t* __restrict__ Whi, const uint32_t* __restrict__ Wlo,
        const float* __restrict__ bias, float* __restrict__ C){
    extern __shared__ uint32_t smu[];
    int tid = threadIdx.x, lane = tid & 31, wid = tid >> 5;
    int brow = blockIdx.y * 128, bcol = blockIdx.x * 128;
    int mw = wid & 1, nw = wid >> 1;
    int gid = lane >> 2, tig = lane & 3;
    constexpr int NC = K / 32;       // chunks of 32 floats (16 uint32)
    constexpr int K2 = K / 2;        // global row stride in uint32

    auto load_stage = [&](int s, int kc){
        uint32_t* base = smu + s * STG_U32;
        uint32_t sAh = smem_u32(base);
        uint32_t sWh = smem_u32(base + 128 * ST2);
        uint32_t sWl = smem_u32(base + 256 * ST2);
        int k0 = kc * 16;
#pragma unroll
        for (int i = 0; i < 2; i++){
            int idx = tid + i * 256;
            int r = idx >> 2;                  // 0..127
            int c4 = (idx & 3) << 2;           // uint32 offset within chunk
            uint32_t soff = (uint32_t)(r * ST2 + c4) * 4u;
            int gr = brow + r;
            cp_async16(sAh + soff, Ahi + (size_t)gr * K2 + k0 + c4, (gr < NNODES) ? 16 : 0);
            cp_async16(sWh + soff, Whi + (size_t)(bcol + r) * K2 + k0 + c4, 16);
            cp_async16(sWl + soff, Wlo + (size_t)(bcol + r) * K2 + k0 + c4, 16);
        }
        CP_COMMIT();
    };

    float acc[4][4][4];
#pragma unroll
    for (int i = 0; i < 4; i++)
#pragma unroll
        for (int j = 0; j < 4; j++)
#pragma unroll
            for (int l = 0; l < 4; l++) acc[i][j][l] = 0.0f;

    load_stage(0, 0);
    if (NC > 1) load_stage(1, 1);

    for (int kc = 0; kc < NC; kc++){
        int buf = kc & 1;
        if (kc + 1 < NC) { CP_WAIT(1); } else { CP_WAIT(0); }
        __syncthreads();
        const uint32_t* sAh = smu + buf * STG_U32;
        const uint32_t* sWh = sAh + 128 * ST2;
        const uint32_t* sWl = sAh + 256 * ST2;
#pragma unroll
        for (int ks = 0; ks < 2; ks++){        // two K=16 steps per 32-float chunk
            int kb = ks * 8;                   // uint32 offset
            uint32_t ah[4][4];
#pragma unroll
            for (int sm2 = 0; sm2 < 4; sm2++){
                int row = mw * 64 + sm2 * 16 + gid;
                int r0 = row * ST2 + kb + tig;
                int r1 = (row + 8) * ST2 + kb + tig;
                ah[sm2][0] = sAh[r0]; ah[sm2][1] = sAh[r1];
                ah[sm2][2] = sAh[r0 + 4]; ah[sm2][3] = sAh[r1 + 4];
            }
#pragma unroll
            for (int sn = 0; sn < 4; sn++){
                int col = nw * 32 + sn * 8 + gid;
                int c0 = col * ST2 + kb + tig;
                uint32_t wh0 = sWh[c0], wh1 = sWh[c0 + 4];
                uint32_t wl0 = sWl[c0], wl1 = sWl[c0 + 4];
#pragma unroll
                for (int sm2 = 0; sm2 < 4; sm2++){
                    mma_bf16(acc[sm2][sn], ah[sm2], wh0, wh1);
                    mma_bf16(acc[sm2][sn], ah[sm2], wl0, wl1);
                }
            }
        }
        __syncthreads();
        if (kc + 2 < NC) load_stage(buf, kc + 2);
    }

#pragma unroll
    for (int sm2 = 0; sm2 < 4; sm2++){
#pragma unroll
        for (int sn = 0; sn < 4; sn++){
            int row = brow + mw * 64 + sm2 * 16 + gid;
            int col = bcol + nw * 32 + sn * 8 + tig * 2;
            float2 bb = *(const float2*)(bias + col);
            if (row < NNODES){
                float2 o; o.x = acc[sm2][sn][0] + bb.x; o.y = acc[sm2][sn][1] + bb.y;
                *(float2*)(C + (size_t)row * MOUT + col) = o;
            }
            if (row + 8 < NNODES){
                float2 o; o.x = acc[sm2][sn][2] + bb.x; o.y = acc[sm2][sn][3] + bb.y;
                *(float2*)(C + (size_t)(row + 8) * MOUT + col) = o;
            }
        }
    }
}

// ---------------- mean over nodes ----------------
__global__ void zero384_kernel(){ g_sums[threadIdx.x] = 0.0f; }

__global__ void mean_kernel(const float* __restrict__ U){
    int t = threadIdx.x;
    int start = blockIdx.x * 250;
    int end = start + 250;
    float s = 0.0f;
    for (int nn = start; nn < end; nn++) s += U[(size_t)nn * 384 + t];
    atomicAdd(&g_sums[t], s);
}

// ---------------- final classifier head ----------------
__global__ void classify_kernel(const float* __restrict__ Wc, const float* __restrict__ bc,
                                float* __restrict__ out){
    __shared__ float sh_hm[384];
    __shared__ float sh_warp[16];
    __shared__ float sh_mx[10];
    __shared__ float sh_factor;
    int t = threadIdx.x, lane = t & 31, wid = t >> 5;
    float v = 0.0f;
    if (t < 384) v = g_sums[t] * (1.0f / (float)NNODES);
    if (t == 0) v = 0.0f;
    if (t < 384) sh_hm[t] = v;
    float s = warpSum(v * v);
    if (lane == 0) sh_warp[wid] = s;
    __syncthreads();
    if (t == 0){
        float S = 0.0f;
        for (int i = 0; i < 16; i++) S += sh_warp[i];
        float nrm = sqrtf(S + EPSF);
        float dist = arcosh_cl(0.0f + EPSF);
        sh_factor = dist / nrm;
    }
    __syncthreads();
    float factor = sh_factor;
    if (wid < 9){
        float d = 0.0f;
        for (int j = lane; j < 383; j += 32) d += sh_hm[j + 1] * factor * Wc[wid * 383 + j];
        d = warpSum(d);
        if (lane == 0) sh_mx[wid + 1] = d + bc[wid];
    }
    if (t == 0) sh_mx[0] = 0.0f;
    __syncthreads();
    if (t == 0){
        float mx[10];
#pragma unroll
        for (int i = 0; i < 10; i++) mx[i] = sh_mx[i];
        float S = 0.0f;
        for (int i = 1; i < 10; i++) S += mx[i] * mx[i];
        float n = sqrtf(fmaxf(S + EPSF, 1e-6f));
        float f = sinhf(fminf(n, 50.0f)) / n;
        float fS = f * f * S;
        float hc[10];
        bool cond = (S == 0.0f);
        if (cond){
            for (int i = 0; i < 10; i++) hc[i] = 0.0f;
        } else {
            hc[0] = sqrtf(1.0f + fS);
            for (int i = 1; i < 10; i++) hc[i] = f * mx[i];
        }
        for (int i = 0; i < 10; i++) out[i] = hc[i];
        float x0c = fmaxf(hc[0] + EPSF, 1.0f + EPSF);
        float dd = logf(x0c + sqrtf(x0c * x0c - 1.0f));
        float tn = 0.0f;
        for (int i = 1; i < 10; i++) tn += hc[i] * hc[i];
        float nr = sqrtf(tn + EPSF);
        float gf = dd / nr;
        float lt[10]; lt[0] = 0.0f;
        for (int i = 1; i < 10; i++) lt[i] = gf * hc[i];
        float mmax = lt[0];
        for (int i = 1; i < 10; i++) mmax = fmaxf(mmax, lt[i]);
        float e[10], se = 0.0f;
        for (int i = 0; i < 10; i++){ e[i] = expf(lt[i] - mmax); se += e[i]; }
        float p[10];
        for (int i = 0; i < 10; i++) p[i] = e[i] / se;
        p[0] = 0.0f;
        float S3 = 0.0f;
        for (int i = 1; i < 10; i++) S3 += p[i] * p[i];
        float n3 = sqrtf(fmaxf(S3 + EPSF, 1e-6f));
        float f3 = sinhf(fminf(n3, 50.0f)) / n3;
        float f3S = f3 * f3 * S3;
        out[10] = sqrtf(1.0f + f3S);
        for (int i = 1; i < 10; i++) out[10 + i] = f3 * p[i];
    }
}

// ---------------- launch ----------------
extern "C" void kernel_launch(void* const* d_in, const int* in_sizes, int n_in,
                              void* d_out, int out_size){
    const float* x  = (const float*)d_in[0];
    const int*   ei = (const int*)  d_in[1];
    const float* W0 = (const float*)d_in[2];
    const float* b0 = (const float*)d_in[3];
    const float* W1 = (const float*)d_in[4];
    const float* b1 = (const float*)d_in[5];
    const float* W2 = (const float*)d_in[6];
    const float* b2 = (const float*)d_in[7];
    const float* Wc = (const float*)d_in[8];
    const float* bc = (const float*)d_in[9];
    float* out = (float*)d_out;

    uint32_t *pW0h,*pW0l,*pW1h,*pW1l,*pW2h,*pW2l,*pAh;
    float *pbp0,*pbp1,*pbp2,*pB,*pV;
    cudaGetSymbolAddress((void**)&pW0h, g_W0hi);
    cudaGetSymbolAddress((void**)&pW0l, g_W0lo);
    cudaGetSymbolAddress((void**)&pW1h, g_W1hi);
    cudaGetSymbolAddress((void**)&pW1l, g_W1lo);
    cudaGetSymbolAddress((void**)&pW2h, g_W2hi);
    cudaGetSymbolAddress((void**)&pW2l, g_W2lo);
    cudaGetSymbolAddress((void**)&pbp0, g_bp0);
    cudaGetSymbolAddress((void**)&pbp1, g_bp1);
    cudaGetSymbolAddress((void**)&pbp2, g_bp2);
    cudaGetSymbolAddress((void**)&pAh,  g_Ahi);
    cudaGetSymbolAddress((void**)&pB,   g_bufB);
    cudaGetSymbolAddress((void**)&pV,   g_v);

    cudaFuncSetAttribute(mma_gemm<128,128>, cudaFuncAttributeMaxDynamicSharedMemorySize, MMA_SMEM);
    cudaFuncSetAttribute(mma_gemm<128,256>, cudaFuncAttributeMaxDynamicSharedMemorySize, MMA_SMEM);
    cudaFuncSetAttribute(mma_gemm<256,384>, cudaFuncAttributeMaxDynamicSharedMemorySize, MMA_SMEM);

    prep_kernel<128,128><<<(128*64 + 255)/256, 256>>>(W0, b0, pW0h, pW0l, pbp0);
    prep_kernel<256,128><<<(256*64 + 255)/256, 256>>>(W1, b1, pW1h, pW1l, pbp1);
    prep_kernel<384,256><<<(384*128 + 255)/256, 256>>>(W2, b2, pW2h, pW2l, pbp2);

    const int RB = (NNODES + 7) / 8;
    const int NT = (NNODES + 127) / 128;   // 391 row tiles

    lmap0_kernel<<<RB, 256>>>(x);
    scatter_kernel<<<(NEDGES + 7)/8, 256>>>(ei);
    manpre_kernel<<<RB, 256>>>();

    mma_gemm<128,128><<<dim3(1, NT), 256, MMA_SMEM>>>(pAh, pW0h, pW0l, pbp0, pV);
    rowpost_kernel<128><<<RB, 256>>>(pV, pAh);
    mma_gemm<128,256><<<dim3(2, NT), 256, MMA_SMEM>>>(pAh, pW1h, pW1l, pbp1, pV);
    rowpost_kernel<256><<<RB, 256>>>(pV, pAh);
    mma_gemm<256,384><<<dim3(3, NT), 256, MMA_SMEM>>>(pAh, pW2h, pW2l, pbp2, pV);
    rowpost_final_kernel<<<RB, 256>>>(pV, pB);

    zero384_kernel<<<1, 384>>>();
    mean_kernel<<<200, 384>>>(pB);
    classify_kernel<<<1, 512>>>(Wc, bc, out);
}

// round 12
// speedup vs baseline: 1.7126x; 1.1910x over previous
#include <cuda_runtime.h>
#include <cuda_bf16.h>
#include <cstdint>

#define NNODES 50000
#define NEDGES 800000
#define EPSF 1e-7f

// ---------------- static device scratch ----------------
__device__ __align__(16) uint32_t g_u0b [NNODES*64];    // u0 packed bf16x2 (128 vals)
__device__ __align__(16) uint32_t g_accb[NNODES*64];    // acc packed bf16x2
__device__ __align__(16) uint32_t g_v   [NNODES*192];   // GEMM C packed bf16x2 (max 384)
__device__ __align__(16) uint32_t g_bufBb[NNODES*192];  // final ht packed bf16x2
__device__ __align__(16) uint32_t g_Ahi[NNODES*128];    // A plane bf16x2 (max K=256)
__device__ __align__(16) uint32_t g_W0hi[128*64];
__device__ __align__(16) uint32_t g_W0lo[128*64];
__device__ __align__(16) uint32_t g_W1hi[256*64];
__device__ __align__(16) uint32_t g_W1lo[256*64];
__device__ __align__(16) uint32_t g_W2hi[384*128];
__device__ __align__(16) uint32_t g_W2lo[384*128];
__device__ __align__(16) float g_bp0[128];
__device__ __align__(16) float g_bp1[256];
__device__ __align__(16) float g_bp2[384];
__device__ float g_sums[384];

// ---------------- helpers ----------------
__device__ __forceinline__ float warpSum(float v){
#pragma unroll
    for (int o = 16; o > 0; o >>= 1) v += __shfl_xor_sync(0xffffffffu, v, o);
    return v;
}
__device__ __forceinline__ float arcosh_cl(float x){
    x = fmaxf(x, 1.0f + EPSF);
    return logf(x + sqrtf(x * x - 1.0f));
}
__device__ __forceinline__ void bfsplit(float x, uint16_t& hi, uint16_t& lo){
    __nv_bfloat16 h = __float2bfloat16_rn(x);
    hi = __bfloat16_as_ushort(h);
    float r = x - __bfloat162float(h);
    lo = __bfloat16_as_ushort(__float2bfloat16_rn(r));
}
__device__ __forceinline__ void bfpack2(float x, float y, uint32_t& hi2, uint32_t& lo2){
    uint16_t h0, l0, h1, l1;
    bfsplit(x, h0, l0);
    bfsplit(y, h1, l1);
    hi2 = (uint32_t)h0 | ((uint32_t)h1 << 16);
    lo2 = (uint32_t)l0 | ((uint32_t)l1 << 16);
}
__device__ __forceinline__ uint32_t bfpack2hi(float x, float y){
    uint16_t h0 = __bfloat16_as_ushort(__float2bfloat16_rn(x));
    uint16_t h1 = __bfloat16_as_ushort(__float2bfloat16_rn(y));
    return (uint32_t)h0 | ((uint32_t)h1 << 16);
}
// unpack bf16x2 -> two floats (lo = first/even element)
__device__ __forceinline__ void bfunpack2(uint32_t p, float& lo, float& hi){
    lo = __uint_as_float(p << 16);
    hi = __uint_as_float(p & 0xffff0000u);
}
__device__ __forceinline__ void mma_bf16(float* c, const uint32_t* a, uint32_t b0, uint32_t b1){
    asm volatile(
        "mma.sync.aligned.m16n8k16.row.col.f32.bf16.bf16.f32 "
        "{%0,%1,%2,%3}, {%4,%5,%6,%7}, {%8,%9}, {%0,%1,%2,%3};"
        : "+f"(c[0]), "+f"(c[1]), "+f"(c[2]), "+f"(c[3])
        : "r"(a[0]), "r"(a[1]), "r"(a[2]), "r"(a[3]), "r"(b0), "r"(b1));
}
__device__ __forceinline__ uint32_t smem_u32(const void* p){
    return (uint32_t)__cvta_generic_to_shared(p);
}
__device__ __forceinline__ void cp_async16(uint32_t sdst, const void* gsrc, int srcsize){
    asm volatile("cp.async.cg.shared.global [%0], [%1], 16, %2;"
                 :: "r"(sdst), "l"(gsrc), "r"(srcsize) : "memory");
}
#define CP_COMMIT() asm volatile("cp.async.commit_group;" ::: "memory")
#define CP_WAIT(n)  asm volatile("cp.async.wait_group %0;" :: "n"(n) : "memory")

// ---------------- weight padding + bf16 hi/lo split ----------------
template<int MPAD, int KPAD>
__global__ void prep_kernel(const float* __restrict__ W, const float* __restrict__ b,
                            uint32_t* __restrict__ Whi, uint32_t* __restrict__ Wlo,
                            float* __restrict__ bp){
    int idx = blockIdx.x * blockDim.x + threadIdx.x;
    constexpr int K2 = KPAD / 2;
    if (idx < MPAD * K2){
        int m = idx / K2, kk = idx % K2;
        int k0 = 2 * kk, k1 = 2 * kk + 1;
        float w0 = (m >= 1 && k0 >= 1) ? W[(m - 1) * (KPAD - 1) + (k0 - 1)] : 0.0f;
        float w1 = (m >= 1) ? W[(m - 1) * (KPAD - 1) + (k1 - 1)] : 0.0f;
        uint32_t h2, l2;
        bfpack2(w0, w1, h2, l2);
        Whi[idx] = h2;
        Wlo[idx] = l2;
    }
    if (idx < MPAD) bp[idx] = (idx >= 1) ? b[idx - 1] : 0.0f;
}

// ---------------- log_map_zero(x) -> u0b, accb (packed bf16x2) ----------------
__global__ void lmap0_kernel(const float* __restrict__ x){
    int warp = (blockIdx.x * blockDim.x + threadIdx.x) >> 5;
    if (warp >= NNODES) return;
    int lane = threadIdx.x & 31;
    float4 a = ((const float4*)x)[(size_t)warp * 32 + lane];
    float y0 = __shfl_sync(0xffffffffu, a.x, 0);
    float s = a.x*a.x + a.y*a.y + a.z*a.z + a.w*a.w;
    if (lane == 0) s = a.y*a.y + a.z*a.z + a.w*a.w;
    float S = warpSum(s);
    float dist = arcosh_cl(y0 + EPSF);
    float g = dist / sqrtf(S + EPSF);
    float ux = (lane == 0) ? 0.0f : g * a.x;
    uint2 h;
    h.x = bfpack2hi(ux, g * a.y);
    h.y = bfpack2hi(g * a.z, g * a.w);
    ((uint2*)g_u0b )[(size_t)warp * 32 + lane] = h;
    ((uint2*)g_accb)[(size_t)warp * 32 + lane] = h;
}

// ---------------- segment_sum via vector bf16x2 red.global (half-warp/edge) ----------------
__global__ void scatter_kernel(const int* __restrict__ ei){
    int e = (blockIdx.x * blockDim.x + threadIdx.x) >> 4;
    if (e >= NEDGES) return;
    int l16 = threadIdx.x & 15;
    int src = ei[e];
    int dst = ei[NEDGES + e];
    uint4 v = ((const uint4*)g_u0b)[(size_t)src * 16 + l16];
    uint32_t* addr = g_accb + (size_t)dst * 64 + l16 * 4;
    asm volatile("red.global.add.noftz.v4.bf16x2 [%0], {%1,%2,%3,%4};"
                 :: "l"(addr), "r"(v.x), "r"(v.y), "r"(v.z), "r"(v.w) : "memory");
}

// ---------------- log_map(exp_map(acc)) -> A plane (K=128) ----------------
__global__ void manpre_kernel(){
    int warp = (blockIdx.x * blockDim.x + threadIdx.x) >> 5;
    if (warp >= NNODES) return;
    int lane = threadIdx.x & 31;
    uint2 p = ((const uint2*)g_accb)[(size_t)warp * 32 + lane];
    float ax, ay, az, aw;
    bfunpack2(p.x, ax, ay);
    bfunpack2(p.y, az, aw);
    float s = ax*ax + ay*ay + az*az + aw*aw;
    float S = warpSum(s);
    float n = sqrtf(fmaxf(S + EPSF, 1e-6f));
    float f = sinhf(fminf(n, 50.0f)) / n;
    float fS = f * f * S;
    float first = sqrtf(1.0f + fS);
    float dist = arcosh_cl(first + EPSF);
    float g = dist / sqrtf(fS + EPSF) * f;
    uint2 h;
    h.x = bfpack2hi(g*ax, g*ay);
    h.y = bfpack2hi(g*az, g*aw);
    ((uint2*)g_Ahi)[(size_t)warp * 32 + lane] = h;
}

// ---------------- post-GEMM chain (bf16 in) -> bf16 A plane ----------------
template<int MP>
__global__ void rowpost_kernel(const uint32_t* __restrict__ V, uint32_t* __restrict__ Uhi){
    int warp = (blockIdx.x * blockDim.x + threadIdx.x) >> 5;
    if (warp >= NNODES) return;
    int lane = threadIdx.x & 31;
    constexpr int PL = MP / 128;
    const uint2* vr = (const uint2*)(V + (size_t)warp * (MP / 2));
    float a[PL][4];
    float s = 0.0f;
#pragma unroll
    for (int i = 0; i < PL; i++){
        uint2 p = vr[i * 32 + lane];
        bfunpack2(p.x, a[i][0], a[i][1]);
        bfunpack2(p.y, a[i][2], a[i][3]);
        s += a[i][0]*a[i][0] + a[i][1]*a[i][1] + a[i][2]*a[i][2] + a[i][3]*a[i][3];
    }
    float S = warpSum(s);
    float n = sqrtf(fmaxf(S + EPSF, 1e-6f));
    float f = sinhf(fminf(n, 50.0f)) / n;
    float fS = f * f * S;
    float first = sqrtf(1.0f + fS);
    float dist = arcosh_cl(first + EPSF);
    float g1 = dist / sqrtf(fS + EPSF) * f;
    float s2 = 0.0f;
#pragma unroll
    for (int i = 0; i < PL; i++){
#pragma unroll
        for (int j = 0; j < 4; j++){
            a[i][j] = fmaxf(g1 * a[i][j], 0.0f);
            s2 += a[i][j] * a[i][j];
        }
    }
    float S2 = warpSum(s2);
    float n2 = sqrtf(fmaxf(S2 + EPSF, 1e-6f));
    float f2 = sinhf(fminf(n2, 50.0f)) / n2;
    float f2S = f2 * f2 * S2;
    float first2 = sqrtf(1.0f + f2S);
    float dist2 = arcosh_cl(first2 + EPSF);
    float g2 = dist2 / sqrtf(f2S + EPSF) * f2;
#pragma unroll
    for (int i = 0; i < PL; i++){
        uint2 h;
        h.x = bfpack2hi(g2*a[i][0], g2*a[i][1]);
        h.y = bfpack2hi(g2*a[i][2], g2*a[i][3]);
        ((uint2*)Uhi)[(size_t)warp * (MP / 4) + i * 32 + lane] = h;
    }
}

// ---------------- final rowpost (MP=384, bf16 in) -> packed bf16 ht ----------------
__global__ void rowpost_final_kernel(const uint32_t* __restrict__ V, uint32_t* __restrict__ Ub){
    int warp = (blockIdx.x * blockDim.x + threadIdx.x) >> 5;
    if (warp >= NNODES) return;
    int lane = threadIdx.x & 31;
    const uint2* vr = (const uint2*)(V + (size_t)warp * 192);
    float a[3][4];
    float s = 0.0f;
#pragma unroll
    for (int i = 0; i < 3; i++){
        uint2 p = vr[i * 32 + lane];
        bfunpack2(p.x, a[i][0], a[i][1]);
        bfunpack2(p.y, a[i][2], a[i][3]);
        s += a[i][0]*a[i][0] + a[i][1]*a[i][1] + a[i][2]*a[i][2] + a[i][3]*a[i][3];
    }
    float S = warpSum(s);
    float n = sqrtf(fmaxf(S + EPSF, 1e-6f));
    float f = sinhf(fminf(n, 50.0f)) / n;
    float fS = f * f * S;
    float first = sqrtf(1.0f + fS);
    float dist = arcosh_cl(first + EPSF);
    float g1 = dist / sqrtf(fS + EPSF) * f;
    float s2 = 0.0f;
#pragma unroll
    for (int i = 0; i < 3; i++){
#pragma unroll
        for (int j = 0; j < 4; j++){
            a[i][j] = fmaxf(g1 * a[i][j], 0.0f);
            s2 += a[i][j] * a[i][j];
        }
    }
    float S2 = warpSum(s2);
    float n2 = sqrtf(fmaxf(S2 + EPSF, 1e-6f));
    float f2 = sinhf(fminf(n2, 50.0f)) / n2;
    float f2S = f2 * f2 * S2;
    float first2 = sqrtf(1.0f + f2S);
    float dist2 = arcosh_cl(first2 + EPSF);
    float g2 = dist2 / sqrtf(f2S + EPSF) * f2;
#pragma unroll
    for (int i = 0; i < 3; i++){
        uint2 h;
        h.x = bfpack2hi(g2*a[i][0], g2*a[i][1]);
        h.y = bfpack2hi(g2*a[i][2], g2*a[i][3]);
        ((uint2*)Ub)[(size_t)warp * 96 + i * 32 + lane] = h;
    }
}

// ---------------- cp.async double-buffered bf16 2-MMA GEMM (128x128 tile) ----------------
// A bf16, W = Whi + Wlo. C = A.W^T + bias, stored packed bf16x2.
#define ST2 20
static constexpr int STG_U32 = 3 * 128 * ST2;
static constexpr int MMA_SMEM = 2 * STG_U32 * 4;       // 61440 B

template<int K, int MOUT>
__global__ void __launch_bounds__(256, 2) mma_gemm(
        const uint32_t* __restrict__ Ahi,
        const uint32_t* __restrict__ Whi, const uint32_t* __restrict__ Wlo,
        const float* __restrict__ bias, uint32_t* __restrict__ C){
    extern __shared__ uint32_t smu[];
    int tid = threadIdx.x, lane = tid & 31, wid = tid >> 5;
    int brow = blockIdx.y * 128, bcol = blockIdx.x * 128;
    int mw = wid & 1, nw = wid >> 1;
    int gid = lane >> 2, tig = lane & 3;
    constexpr int NC = K / 32;
    constexpr int K2 = K / 2;

    auto load_stage = [&](int s, int kc){
        uint32_t* base = smu + s * STG_U32;
        uint32_t sAh = smem_u32(base);
        uint32_t sWh = smem_u32(base + 128 * ST2);
        uint32_t sWl = smem_u32(base + 256 * ST2);
        int k0 = kc * 16;
#pragma unroll
        for (int i = 0; i < 2; i++){
            int idx = tid + i * 256;
            int r = idx >> 2;
            int c4 = (idx & 3) << 2;
            uint32_t soff = (uint32_t)(r * ST2 + c4) * 4u;
            int gr = brow + r;
            cp_async16(sAh + soff, Ahi + (size_t)gr * K2 + k0 + c4, (gr < NNODES) ? 16 : 0);
            cp_async16(sWh + soff, Whi + (size_t)(bcol + r) * K2 + k0 + c4, 16);
            cp_async16(sWl + soff, Wlo + (size_t)(bcol + r) * K2 + k0 + c4, 16);
        }
        CP_COMMIT();
    };

    float acc[4][4][4];
#pragma unroll
    for (int i = 0; i < 4; i++)
#pragma unroll
        for (int j = 0; j < 4; j++)
#pragma unroll
            for (int l = 0; l < 4; l++) acc[i][j][l] = 0.0f;

    load_stage(0, 0);
    if (NC > 1) load_stage(1, 1);

    for (int kc = 0; kc < NC; kc++){
        int buf = kc & 1;
        if (kc + 1 < NC) { CP_WAIT(1); } else { CP_WAIT(0); }
        __syncthreads();
        const uint32_t* sAh = smu + buf * STG_U32;
        const uint32_t* sWh = sAh + 128 * ST2;
        const uint32_t* sWl = sAh + 256 * ST2;
#pragma unroll
        for (int ks = 0; ks < 2; ks++){
            int kb = ks * 8;
            uint32_t ah[4][4];
#pragma unroll
            for (int sm2 = 0; sm2 < 4; sm2++){
                int row = mw * 64 + sm2 * 16 + gid;
                int r0 = row * ST2 + kb + tig;
                int r1 = (row + 8) * ST2 + kb + tig;
                ah[sm2][0] = sAh[r0]; ah[sm2][1] = sAh[r1];
                ah[sm2][2] = sAh[r0 + 4]; ah[sm2][3] = sAh[r1 + 4];
            }
#pragma unroll
            for (int sn = 0; sn < 4; sn++){
                int col = nw * 32 + sn * 8 + gid;
                int c0 = col * ST2 + kb + tig;
                uint32_t wh0 = sWh[c0], wh1 = sWh[c0 + 4];
                uint32_t wl0 = sWl[c0], wl1 = sWl[c0 + 4];
#pragma unroll
                for (int sm2 = 0; sm2 < 4; sm2++){
                    mma_bf16(acc[sm2][sn], ah[sm2], wh0, wh1);
                    mma_bf16(acc[sm2][sn], ah[sm2], wl0, wl1);
                }
            }
        }
        __syncthreads();
        if (kc + 2 < NC) load_stage(buf, kc + 2);
    }

#pragma unroll
    for (int sm2 = 0; sm2 < 4; sm2++){
#pragma unroll
        for (int sn = 0; sn < 4; sn++){
            int row = brow + mw * 64 + sm2 * 16 + gid;
            int col = bcol + nw * 32 + sn * 8 + tig * 2;     // even
            float2 bb = *(const float2*)(bias + col);
            if (row < NNODES){
                C[(size_t)row * (MOUT/2) + (col >> 1)] =
                    bfpack2hi(acc[sm2][sn][0] + bb.x, acc[sm2][sn][1] + bb.y);
            }
            if (row + 8 < NNODES){
                C[(size_t)(row + 8) * (MOUT/2) + (col >> 1)] =
                    bfpack2hi(acc[sm2][sn][2] + bb.x, acc[sm2][sn][3] + bb.y);
            }
        }
    }
}

// ---------------- mean over nodes (bf16 in, fp32 sums) ----------------
__global__ void zero384_kernel(){ g_sums[threadIdx.x] = 0.0f; }

__global__ void mean_kernel(const uint32_t* __restrict__ U){
    int t = threadIdx.x;              // 192 threads, one u32 column each
    int start = blockIdx.x * 250;
    int end = start + 250;
    float s0 = 0.0f, s1 = 0.0f;
    for (int nn = start; nn < end; nn++){
        uint32_t p = U[(size_t)nn * 192 + t];
        float lo, hi;
        bfunpack2(p, lo, hi);
        s0 += lo; s1 += hi;
    }
    atomicAdd(&g_sums[2 * t],     s0);
    atomicAdd(&g_sums[2 * t + 1], s1);
}

// ---------------- final classifier head ----------------
__global__ void classify_kernel(const float* __restrict__ Wc, const float* __restrict__ bc,
                                float* __restrict__ out){
    __shared__ float sh_hm[384];
    __shared__ float sh_warp[16];
    __shared__ float sh_mx[10];
    __shared__ float sh_factor;
    int t = threadIdx.x, lane = t & 31, wid = t >> 5;
    float v = 0.0f;
    if (t < 384) v = g_sums[t] * (1.0f / (float)NNODES);
    if (t == 0) v = 0.0f;
    if (t < 384) sh_hm[t] = v;
    float s = warpSum(v * v);
    if (lane == 0) sh_warp[wid] = s;
    __syncthreads();
    if (t == 0){
        float S = 0.0f;
        for (int i = 0; i < 16; i++) S += sh_warp[i];
        float nrm = sqrtf(S + EPSF);
        float dist = arcosh_cl(0.0f + EPSF);
        sh_factor = dist / nrm;
    }
    __syncthreads();
    float factor = sh_factor;
    if (wid < 9){
        float d = 0.0f;
        for (int j = lane; j < 383; j += 32) d += sh_hm[j + 1] * factor * Wc[wid * 383 + j];
        d = warpSum(d);
        if (lane == 0) sh_mx[wid + 1] = d + bc[wid];
    }
    if (t == 0) sh_mx[0] = 0.0f;
    __syncthreads();
    if (t == 0){
        float mx[10];
#pragma unroll
        for (int i = 0; i < 10; i++) mx[i] = sh_mx[i];
        float S = 0.0f;
        for (int i = 1; i < 10; i++) S += mx[i] * mx[i];
        float n = sqrtf(fmaxf(S + EPSF, 1e-6f));
        float f = sinhf(fminf(n, 50.0f)) / n;
        float fS = f * f * S;
        float hc[10];
        bool cond = (S == 0.0f);
        if (cond){
            for (int i = 0; i < 10; i++) hc[i] = 0.0f;
        } else {
            hc[0] = sqrtf(1.0f + fS);
            for (int i = 1; i < 10; i++) hc[i] = f * mx[i];
        }
        for (int i = 0; i < 10; i++) out[i] = hc[i];
        float x0c = fmaxf(hc[0] + EPSF, 1.0f + EPSF);
        float dd = logf(x0c + sqrtf(x0c * x0c - 1.0f));
        float tn = 0.0f;
        for (int i = 1; i < 10; i++) tn += hc[i] * hc[i];
        float nr = sqrtf(tn + EPSF);
        float gf = dd / nr;
        float lt[10]; lt[0] = 0.0f;
        for (int i = 1; i < 10; i++) lt[i] = gf * hc[i];
        float mmax = lt[0];
        for (int i = 1; i < 10; i++) mmax = fmaxf(mmax, lt[i]);
        float e[10], se = 0.0f;
        for (int i = 0; i < 10; i++){ e[i] = expf(lt[i] - mmax); se += e[i]; }
        float p[10];
        for (int i = 0; i < 10; i++) p[i] = e[i] / se;
        p[0] = 0.0f;
        float S3 = 0.0f;
        for (int i = 1; i < 10; i++) S3 += p[i] * p[i];
        float n3 = sqrtf(fmaxf(S3 + EPSF, 1e-6f));
        float f3 = sinhf(fminf(n3, 50.0f)) / n3;
        float f3S = f3 * f3 * S3;
        out[10] = sqrtf(1.0f + f3S);
        for (int i = 1; i < 10; i++) out[10 + i] = f3 * p[i];
    }
}

// ---------------- launch ----------------
extern "C" void kernel_launch(void* const* d_in, const int* in_sizes, int n_in,
                              void* d_out, int out_size){
    const float* x  = (const float*)d_in[0];
    const int*   ei = (const int*)  d_in[1];
    const float* W0 = (const float*)d_in[2];
    const float* b0 = (const float*)d_in[3];
    const float* W1 = (const float*)d_in[4];
    const float* b1 = (const float*)d_in[5];
    const float* W2 = (const float*)d_in[6];
    const float* b2 = (const float*)d_in[7];
    const float* Wc = (const float*)d_in[8];
    const float* bc = (const float*)d_in[9];
    float* out = (float*)d_out;

    uint32_t *pW0h,*pW0l,*pW1h,*pW1l,*pW2h,*pW2l,*pAh,*pV,*pBb;
    float *pbp0,*pbp1,*pbp2;
    cudaGetSymbolAddress((void**)&pW0h, g_W0hi);
    cudaGetSymbolAddress((void**)&pW0l, g_W0lo);
    cudaGetSymbolAddress((void**)&pW1h, g_W1hi);
    cudaGetSymbolAddress((void**)&pW1l, g_W1lo);
    cudaGetSymbolAddress((void**)&pW2h, g_W2hi);
    cudaGetSymbolAddress((void**)&pW2l, g_W2lo);
    cudaGetSymbolAddress((void**)&pbp0, g_bp0);
    cudaGetSymbolAddress((void**)&pbp1, g_bp1);
    cudaGetSymbolAddress((void**)&pbp2, g_bp2);
    cudaGetSymbolAddress((void**)&pAh,  g_Ahi);
    cudaGetSymbolAddress((void**)&pV,   g_v);
    cudaGetSymbolAddress((void**)&pBb,  g_bufBb);

    cudaFuncSetAttribute(mma_gemm<128,128>, cudaFuncAttributeMaxDynamicSharedMemorySize, MMA_SMEM);
    cudaFuncSetAttribute(mma_gemm<128,256>, cudaFuncAttributeMaxDynamicSharedMemorySize, MMA_SMEM);
    cudaFuncSetAttribute(mma_gemm<256,384>, cudaFuncAttributeMaxDynamicSharedMemorySize, MMA_SMEM);

    prep_kernel<128,128><<<(128*64 + 255)/256, 256>>>(W0, b0, pW0h, pW0l, pbp0);
    prep_kernel<256,128><<<(256*64 + 255)/256, 256>>>(W1, b1, pW1h, pW1l, pbp1);
    prep_kernel<384,256><<<(384*128 + 255)/256, 256>>>(W2, b2, pW2h, pW2l, pbp2);

    const int RB = (NNODES + 7) / 8;
    const int NT = (NNODES + 127) / 128;   // 391 row tiles

    lmap0_kernel<<<RB, 256>>>(x);
    scatter_kernel<<<(NEDGES + 15)/16, 256>>>(ei);   // 16 half-warps (edges) per block
    manpre_kernel<<<RB, 256>>>();

    mma_gemm<128,128><<<dim3(1, NT), 256, MMA_SMEM>>>(pAh, pW0h, pW0l, pbp0, pV);
    rowpost_kernel<128><<<RB, 256>>>(pV, pAh);
    mma_gemm<128,256><<<dim3(2, NT), 256, MMA_SMEM>>>(pAh, pW1h, pW1l, pbp1, pV);
    rowpost_kernel<256><<<RB, 256>>>(pV, pAh);
    mma_gemm<256,384><<<dim3(3, NT), 256, MMA_SMEM>>>(pAh, pW2h, pW2l, pbp2, pV);
    rowpost_final_kernel<<<RB, 256>>>(pV, pBb);

    zero384_kernel<<<1, 384>>>();
    mean_kernel<<<200, 192>>>(pBb);
    classify_kernel<<<1, 512>>>(Wc, bc, out);
}

// round 13
// speedup vs baseline: 1.7559x; 1.0253x over previous
#include <cuda_runtime.h>
#include <cuda_bf16.h>
#include <cstdint>

#define NNODES 50000
#define NEDGES 800000
#define EPSF 1e-7f

// ---------------- static device scratch ----------------
__device__ __align__(16) uint32_t g_u0b [NNODES*64];    // u0 packed bf16x2 (128 vals)
__device__ __align__(16) uint32_t g_accb[NNODES*64];    // acc packed bf16x2
__device__ __align__(16) uint32_t g_v   [NNODES*192];   // GEMM C packed bf16x2 (max 384)
__device__ __align__(16) uint32_t g_bufBb[NNODES*192];  // final ht packed bf16x2
__device__ __align__(16) uint32_t g_Ahi[NNODES*128];    // A plane bf16x2 (max K=256)
__device__ __align__(16) uint32_t g_W0hi[128*64];
__device__ __align__(16) uint32_t g_W0lo[128*64];
__device__ __align__(16) uint32_t g_W1hi[256*64];
__device__ __align__(16) uint32_t g_W1lo[256*64];
__device__ __align__(16) uint32_t g_W2hi[384*128];
__device__ __align__(16) uint32_t g_W2lo[384*128];
__device__ __align__(16) float g_bp0[128];
__device__ __align__(16) float g_bp1[256];
__device__ __align__(16) float g_bp2[384];
__device__ float g_sums[384];

// ---------------- helpers ----------------
__device__ __forceinline__ float warpSum(float v){
#pragma unroll
    for (int o = 16; o > 0; o >>= 1) v += __shfl_xor_sync(0xffffffffu, v, o);
    return v;
}
__device__ __forceinline__ float arcosh_cl(float x){
    x = fmaxf(x, 1.0f + EPSF);
    return logf(x + sqrtf(x * x - 1.0f));
}
__device__ __forceinline__ void bfsplit(float x, uint16_t& hi, uint16_t& lo){
    __nv_bfloat16 h = __float2bfloat16_rn(x);
    hi = __bfloat16_as_ushort(h);
    float r = x - __bfloat162float(h);
    lo = __bfloat16_as_ushort(__float2bfloat16_rn(r));
}
__device__ __forceinline__ void bfpack2(float x, float y, uint32_t& hi2, uint32_t& lo2){
    uint16_t h0, l0, h1, l1;
    bfsplit(x, h0, l0);
    bfsplit(y, h1, l1);
    hi2 = (uint32_t)h0 | ((uint32_t)h1 << 16);
    lo2 = (uint32_t)l0 | ((uint32_t)l1 << 16);
}
__device__ __forceinline__ uint32_t bfpack2hi(float x, float y){
    uint16_t h0 = __bfloat16_as_ushort(__float2bfloat16_rn(x));
    uint16_t h1 = __bfloat16_as_ushort(__float2bfloat16_rn(y));
    return (uint32_t)h0 | ((uint32_t)h1 << 16);
}
__device__ __forceinline__ void bfunpack2(uint32_t p, float& lo, float& hi){
    lo = __uint_as_float(p << 16);
    hi = __uint_as_float(p & 0xffff0000u);
}
__device__ __forceinline__ void mma_bf16(float* c, const uint32_t* a, uint32_t b0, uint32_t b1){
    asm volatile(
        "mma.sync.aligned.m16n8k16.row.col.f32.bf16.bf16.f32 "
        "{%0,%1,%2,%3}, {%4,%5,%6,%7}, {%8,%9}, {%0,%1,%2,%3};"
        : "+f"(c[0]), "+f"(c[1]), "+f"(c[2]), "+f"(c[3])
        : "r"(a[0]), "r"(a[1]), "r"(a[2]), "r"(a[3]), "r"(b0), "r"(b1));
}
__device__ __forceinline__ void ldmx4(uint32_t& r0, uint32_t& r1, uint32_t& r2, uint32_t& r3,
                                      uint32_t addr){
    asm volatile("ldmatrix.sync.aligned.m8n8.x4.shared.b16 {%0,%1,%2,%3}, [%4];"
                 : "=r"(r0), "=r"(r1), "=r"(r2), "=r"(r3) : "r"(addr));
}
__device__ __forceinline__ uint32_t smem_u32(const void* p){
    return (uint32_t)__cvta_generic_to_shared(p);
}
__device__ __forceinline__ void cp_async16(uint32_t sdst, const void* gsrc, int srcsize){
    asm volatile("cp.async.cg.shared.global [%0], [%1], 16, %2;"
                 :: "r"(sdst), "l"(gsrc), "r"(srcsize) : "memory");
}
#define CP_COMMIT() asm volatile("cp.async.commit_group;" ::: "memory")
#define CP_WAIT(n)  asm volatile("cp.async.wait_group %0;" :: "n"(n) : "memory")

// ---------------- weight padding + bf16 hi/lo split ----------------
template<int MPAD, int KPAD>
__global__ void prep_kernel(const float* __restrict__ W, const float* __restrict__ b,
                            uint32_t* __restrict__ Whi, uint32_t* __restrict__ Wlo,
                            float* __restrict__ bp){
    int idx = blockIdx.x * blockDim.x + threadIdx.x;
    constexpr int K2 = KPAD / 2;
    if (idx < MPAD * K2){
        int m = idx / K2, kk = idx % K2;
        int k0 = 2 * kk, k1 = 2 * kk + 1;
        float w0 = (m >= 1 && k0 >= 1) ? W[(m - 1) * (KPAD - 1) + (k0 - 1)] : 0.0f;
        float w1 = (m >= 1) ? W[(m - 1) * (KPAD - 1) + (k1 - 1)] : 0.0f;
        uint32_t h2, l2;
        bfpack2(w0, w1, h2, l2);
        Whi[idx] = h2;
        Wlo[idx] = l2;
    }
    if (idx < MPAD) bp[idx] = (idx >= 1) ? b[idx - 1] : 0.0f;
}

// ---------------- log_map_zero(x) -> u0b, accb (packed bf16x2) ----------------
__global__ void lmap0_kernel(const float* __restrict__ x){
    int warp = (blockIdx.x * blockDim.x + threadIdx.x) >> 5;
    if (warp >= NNODES) return;
    int lane = threadIdx.x & 31;
    float4 a = ((const float4*)x)[(size_t)warp * 32 + lane];
    float y0 = __shfl_sync(0xffffffffu, a.x, 0);
    float s = a.x*a.x + a.y*a.y + a.z*a.z + a.w*a.w;
    if (lane == 0) s = a.y*a.y + a.z*a.z + a.w*a.w;
    float S = warpSum(s);
    float dist = arcosh_cl(y0 + EPSF);
    float g = dist / sqrtf(S + EPSF);
    float ux = (lane == 0) ? 0.0f : g * a.x;
    uint2 h;
    h.x = bfpack2hi(ux, g * a.y);
    h.y = bfpack2hi(g * a.z, g * a.w);
    ((uint2*)g_u0b )[(size_t)warp * 32 + lane] = h;
    ((uint2*)g_accb)[(size_t)warp * 32 + lane] = h;
}

// ---------------- segment_sum via vector bf16x2 red.global (half-warp/edge) ----------------
__global__ void scatter_kernel(const int* __restrict__ ei){
    int e = (blockIdx.x * blockDim.x + threadIdx.x) >> 4;
    if (e >= NEDGES) return;
    int l16 = threadIdx.x & 15;
    int src = ei[e];
    int dst = ei[NEDGES + e];
    uint4 v = ((const uint4*)g_u0b)[(size_t)src * 16 + l16];
    uint32_t* addr = g_accb + (size_t)dst * 64 + l16 * 4;
    asm volatile("red.global.add.noftz.v4.bf16x2 [%0], {%1,%2,%3,%4};"
                 :: "l"(addr), "r"(v.x), "r"(v.y), "r"(v.z), "r"(v.w) : "memory");
}

// ---------------- log_map(exp_map(acc)) -> A plane (K=128) ----------------
__global__ void manpre_kernel(){
    int warp = (blockIdx.x * blockDim.x + threadIdx.x) >> 5;
    if (warp >= NNODES) return;
    int lane = threadIdx.x & 31;
    uint2 p = ((const uint2*)g_accb)[(size_t)warp * 32 + lane];
    float ax, ay, az, aw;
    bfunpack2(p.x, ax, ay);
    bfunpack2(p.y, az, aw);
    float s = ax*ax + ay*ay + az*az + aw*aw;
    float S = warpSum(s);
    float n = sqrtf(fmaxf(S + EPSF, 1e-6f));
    float f = sinhf(fminf(n, 50.0f)) / n;
    float fS = f * f * S;
    float first = sqrtf(1.0f + fS);
    float dist = arcosh_cl(first + EPSF);
    float g = dist / sqrtf(fS + EPSF) * f;
    uint2 h;
    h.x = bfpack2hi(g*ax, g*ay);
    h.y = bfpack2hi(g*az, g*aw);
    ((uint2*)g_Ahi)[(size_t)warp * 32 + lane] = h;
}

// ---------------- post-GEMM chain (bf16 in) -> bf16 A plane ----------------
template<int MP>
__global__ void rowpost_kernel(const uint32_t* __restrict__ V, uint32_t* __restrict__ Uhi){
    int warp = (blockIdx.x * blockDim.x + threadIdx.x) >> 5;
    if (warp >= NNODES) return;
    int lane = threadIdx.x & 31;
    constexpr int PL = MP / 128;
    const uint2* vr = (const uint2*)(V + (size_t)warp * (MP / 2));
    float a[PL][4];
    float s = 0.0f;
#pragma unroll
    for (int i = 0; i < PL; i++){
        uint2 p = vr[i * 32 + lane];
        bfunpack2(p.x, a[i][0], a[i][1]);
        bfunpack2(p.y, a[i][2], a[i][3]);
        s += a[i][0]*a[i][0] + a[i][1]*a[i][1] + a[i][2]*a[i][2] + a[i][3]*a[i][3];
    }
    float S = warpSum(s);
    float n = sqrtf(fmaxf(S + EPSF, 1e-6f));
    float f = sinhf(fminf(n, 50.0f)) / n;
    float fS = f * f * S;
    float first = sqrtf(1.0f + fS);
    float dist = arcosh_cl(first + EPSF);
    float g1 = dist / sqrtf(fS + EPSF) * f;
    float s2 = 0.0f;
#pragma unroll
    for (int i = 0; i < PL; i++){
#pragma unroll
        for (int j = 0; j < 4; j++){
            a[i][j] = fmaxf(g1 * a[i][j], 0.0f);
            s2 += a[i][j] * a[i][j];
        }
    }
    float S2 = warpSum(s2);
    float n2 = sqrtf(fmaxf(S2 + EPSF, 1e-6f));
    float f2 = sinhf(fminf(n2, 50.0f)) / n2;
    float f2S = f2 * f2 * S2;
    float first2 = sqrtf(1.0f + f2S);
    float dist2 = arcosh_cl(first2 + EPSF);
    float g2 = dist2 / sqrtf(f2S + EPSF) * f2;
#pragma unroll
    for (int i = 0; i < PL; i++){
        uint2 h;
        h.x = bfpack2hi(g2*a[i][0], g2*a[i][1]);
        h.y = bfpack2hi(g2*a[i][2], g2*a[i][3]);
        ((uint2*)Uhi)[(size_t)warp * (MP / 4) + i * 32 + lane] = h;
    }
}

// ---------------- final rowpost (MP=384, bf16 in) -> packed bf16 ht ----------------
__global__ void rowpost_final_kernel(const uint32_t* __restrict__ V, uint32_t* __restrict__ Ub){
    int warp = (blockIdx.x * blockDim.x + threadIdx.x) >> 5;
    if (warp >= NNODES) return;
    int lane = threadIdx.x & 31;
    const uint2* vr = (const uint2*)(V + (size_t)warp * 192);
    float a[3][4];
    float s = 0.0f;
#pragma unroll
    for (int i = 0; i < 3; i++){
        uint2 p = vr[i * 32 + lane];
        bfunpack2(p.x, a[i][0], a[i][1]);
        bfunpack2(p.y, a[i][2], a[i][3]);
        s += a[i][0]*a[i][0] + a[i][1]*a[i][1] + a[i][2]*a[i][2] + a[i][3]*a[i][3];
    }
    float S = warpSum(s);
    float n = sqrtf(fmaxf(S + EPSF, 1e-6f));
    float f = sinhf(fminf(n, 50.0f)) / n;
    float fS = f * f * S;
    float first = sqrtf(1.0f + fS);
    float dist = arcosh_cl(first + EPSF);
    float g1 = dist / sqrtf(fS + EPSF) * f;
    float s2 = 0.0f;
#pragma unroll
    for (int i = 0; i < 3; i++){
#pragma unroll
        for (int j = 0; j < 4; j++){
            a[i][j] = fmaxf(g1 * a[i][j], 0.0f);
            s2 += a[i][j] * a[i][j];
        }
    }
    float S2 = warpSum(s2);
    float n2 = sqrtf(fmaxf(S2 + EPSF, 1e-6f));
    float f2 = sinhf(fminf(n2, 50.0f)) / n2;
    float f2S = f2 * f2 * S2;
    float first2 = sqrtf(1.0f + f2S);
    float dist2 = arcosh_cl(first2 + EPSF);
    float g2 = dist2 / sqrtf(f2S + EPSF) * f2;
#pragma unroll
    for (int i = 0; i < 3; i++){
        uint2 h;
        h.x = bfpack2hi(g2*a[i][0], g2*a[i][1]);
        h.y = bfpack2hi(g2*a[i][2], g2*a[i][3]);
        ((uint2*)Ub)[(size_t)warp * 96 + i * 32 + lane] = h;
    }
}

// ---------------- cp.async double-buffered bf16 2-MMA GEMM with ldmatrix ----------------
// A bf16, W = Whi + Wlo. C = A.W^T + bias, stored packed bf16x2.
#define ST2 20
static constexpr int STG_U32 = 3 * 128 * ST2;
static constexpr int MMA_SMEM = 2 * STG_U32 * 4;       // 61440 B

template<int K, int MOUT>
__global__ void __launch_bounds__(256, 2) mma_gemm(
        const uint32_t* __restrict__ Ahi,
        const uint32_t* __restrict__ Whi, const uint32_t* __restrict__ Wlo,
        const float* __restrict__ bias, uint32_t* __restrict__ C){
    extern __shared__ uint32_t smu[];
    int tid = threadIdx.x, lane = tid & 31, wid = tid >> 5;
    int brow = blockIdx.y * 128, bcol = blockIdx.x * 128;
    int mw = wid & 1, nw = wid >> 1;
    int gid = lane >> 2, tig = lane & 3;
    constexpr int NC = K / 32;
    constexpr int K2 = K / 2;

    auto load_stage = [&](int s, int kc){
        uint32_t* base = smu + s * STG_U32;
        uint32_t sAh = smem_u32(base);
        uint32_t sWh = smem_u32(base + 128 * ST2);
        uint32_t sWl = smem_u32(base + 256 * ST2);
        int k0 = kc * 16;
#pragma unroll
        for (int i = 0; i < 2; i++){
            int idx = tid + i * 256;
            int r = idx >> 2;
            int c4 = (idx & 3) << 2;
            uint32_t soff = (uint32_t)(r * ST2 + c4) * 4u;
            int gr = brow + r;
            cp_async16(sAh + soff, Ahi + (size_t)gr * K2 + k0 + c4, (gr < NNODES) ? 16 : 0);
            cp_async16(sWh + soff, Whi + (size_t)(bcol + r) * K2 + k0 + c4, 16);
            cp_async16(sWl + soff, Wlo + (size_t)(bcol + r) * K2 + k0 + c4, 16);
        }
        CP_COMMIT();
    };

    // per-lane ldmatrix address offsets (bytes, within a tile)
    // A: lanes 0-15 -> rows (lane&15) k-lo; 16-31 -> rows (lane&15) k-hi
    uint32_t a_off = (uint32_t)((mw * 64 + (lane & 15)) * ST2 + (lane >> 4) * 4) * 4u;
    // W: pair p covers cols [base+p*16, +8) x2: lanes {0-7,8-15,16-23,24-31} =
    //    {sn0 klo, sn0 khi, sn1 klo, sn1 khi}
    int wsn = (lane >> 4) & 1;
    int wkh = (lane >> 3) & 1;
    uint32_t w_off[2];
#pragma unroll
    for (int p = 0; p < 2; p++)
        w_off[p] = (uint32_t)((nw * 32 + p * 16 + wsn * 8 + (lane & 7)) * ST2 + wkh * 4) * 4u;

    float acc[4][4][4];
#pragma unroll
    for (int i = 0; i < 4; i++)
#pragma unroll
        for (int j = 0; j < 4; j++)
#pragma unroll
            for (int l = 0; l < 4; l++) acc[i][j][l] = 0.0f;

    load_stage(0, 0);
    if (NC > 1) load_stage(1, 1);

    uint32_t sbase = smem_u32(smu);

    for (int kc = 0; kc < NC; kc++){
        int buf = kc & 1;
        if (kc + 1 < NC) { CP_WAIT(1); } else { CP_WAIT(0); }
        __syncthreads();
        uint32_t sAh = sbase + (uint32_t)(buf * STG_U32) * 4u;
        uint32_t sWh = sAh + 128 * ST2 * 4u;
        uint32_t sWl = sAh + 256 * ST2 * 4u;
#pragma unroll
        for (int ks = 0; ks < 2; ks++){
            uint32_t kbb = (uint32_t)(ks * 8) * 4u;   // byte offset of K16 step
            uint32_t ah[4][4];
#pragma unroll
            for (int sm2 = 0; sm2 < 4; sm2++)
                ldmx4(ah[sm2][0], ah[sm2][1], ah[sm2][2], ah[sm2][3],
                      sAh + a_off + (uint32_t)(sm2 * 16 * ST2) * 4u + kbb);
            uint32_t bh0[4], bh1[4], bl0[4], bl1[4];
#pragma unroll
            for (int p = 0; p < 2; p++){
                ldmx4(bh0[2*p], bh1[2*p], bh0[2*p+1], bh1[2*p+1], sWh + w_off[p] + kbb);
                ldmx4(bl0[2*p], bl1[2*p], bl0[2*p+1], bl1[2*p+1], sWl + w_off[p] + kbb);
            }
#pragma unroll
            for (int sn = 0; sn < 4; sn++){
#pragma unroll
                for (int sm2 = 0; sm2 < 4; sm2++){
                    mma_bf16(acc[sm2][sn], ah[sm2], bh0[sn], bh1[sn]);
                    mma_bf16(acc[sm2][sn], ah[sm2], bl0[sn], bl1[sn]);
                }
            }
        }
        __syncthreads();
        if (kc + 2 < NC) load_stage(buf, kc + 2);
    }

#pragma unroll
    for (int sm2 = 0; sm2 < 4; sm2++){
#pragma unroll
        for (int sn = 0; sn < 4; sn++){
            int row = brow + mw * 64 + sm2 * 16 + gid;
            int col = bcol + nw * 32 + sn * 8 + tig * 2;
            float2 bb = *(const float2*)(bias + col);
            if (row < NNODES){
                C[(size_t)row * (MOUT/2) + (col >> 1)] =
                    bfpack2hi(acc[sm2][sn][0] + bb.x, acc[sm2][sn][1] + bb.y);
            }
            if (row + 8 < NNODES){
                C[(size_t)(row + 8) * (MOUT/2) + (col >> 1)] =
                    bfpack2hi(acc[sm2][sn][2] + bb.x, acc[sm2][sn][3] + bb.y);
            }
        }
    }
}

// ---------------- mean over nodes (bf16 in, fp32 sums) ----------------
__global__ void zero384_kernel(){ g_sums[threadIdx.x] = 0.0f; }

__global__ void mean_kernel(const uint32_t* __restrict__ U){
    int t = threadIdx.x;              // 192 threads, one u32 column each
    int start = blockIdx.x * 250;
    int end = start + 250;
    float s0 = 0.0f, s1 = 0.0f;
    for (int nn = start; nn < end; nn++){
        uint32_t p = U[(size_t)nn * 192 + t];
        float lo, hi;
        bfunpack2(p, lo, hi);
        s0 += lo; s1 += hi;
    }
    atomicAdd(&g_sums[2 * t],     s0);
    atomicAdd(&g_sums[2 * t + 1], s1);
}

// ---------------- final classifier head ----------------
__global__ void classify_kernel(const float* __restrict__ Wc, const float* __restrict__ bc,
                                float* __restrict__ out){
    __shared__ float sh_hm[384];
    __shared__ float sh_warp[16];
    __shared__ float sh_mx[10];
    __shared__ float sh_factor;
    int t = threadIdx.x, lane = t & 31, wid = t >> 5;
    float v = 0.0f;
    if (t < 384) v = g_sums[t] * (1.0f / (float)NNODES);
    if (t == 0) v = 0.0f;
    if (t < 384) sh_hm[t] = v;
    float s = warpSum(v * v);
    if (lane == 0) sh_warp[wid] = s;
    __syncthreads();
    if (t == 0){
        float S = 0.0f;
        for (int i = 0; i < 16; i++) S += sh_warp[i];
        float nrm = sqrtf(S + EPSF);
        float dist = arcosh_cl(0.0f + EPSF);
        sh_factor = dist / nrm;
    }
    __syncthreads();
    float factor = sh_factor;
    if (wid < 9){
        float d = 0.0f;
        for (int j = lane; j < 383; j += 32) d += sh_hm[j + 1] * factor * Wc[wid * 383 + j];
        d = warpSum(d);
        if (lane == 0) sh_mx[wid + 1] = d + bc[wid];
    }
    if (t == 0) sh_mx[0] = 0.0f;
    __syncthreads();
    if (t == 0){
        float mx[10];
#pragma unroll
        for (int i = 0; i < 10; i++) mx[i] = sh_mx[i];
        float S = 0.0f;
        for (int i = 1; i < 10; i++) S += mx[i] * mx[i];
        float n = sqrtf(fmaxf(S + EPSF, 1e-6f));
        float f = sinhf(fminf(n, 50.0f)) / n;
        float fS = f * f * S;
        float hc[10];
        bool cond = (S == 0.0f);
        if (cond){
            for (int i = 0; i < 10; i++) hc[i] = 0.0f;
        } else {
            hc[0] = sqrtf(1.0f + fS);
            for (int i = 1; i < 10; i++) hc[i] = f * mx[i];
        }
        for (int i = 0; i < 10; i++) out[i] = hc[i];
        float x0c = fmaxf(hc[0] + EPSF, 1.0f + EPSF);
        float dd = logf(x0c + sqrtf(x0c * x0c - 1.0f));
        float tn = 0.0f;
        for (int i = 1; i < 10; i++) tn += hc[i] * hc[i];
        float nr = sqrtf(tn + EPSF);
        float gf = dd / nr;
        float lt[10]; lt[0] = 0.0f;
        for (int i = 1; i < 10; i++) lt[i] = gf * hc[i];
        float mmax = lt[0];
        for (int i = 1; i < 10; i++) mmax = fmaxf(mmax, lt[i]);
        float e[10], se = 0.0f;
        for (int i = 0; i < 10; i++){ e[i] = expf(lt[i] - mmax); se += e[i]; }
        float p[10];
        for (int i = 0; i < 10; i++) p[i] = e[i] / se;
        p[0] = 0.0f;
        float S3 = 0.0f;
        for (int i = 1; i < 10; i++) S3 += p[i] * p[i];
        float n3 = sqrtf(fmaxf(S3 + EPSF, 1e-6f));
        float f3 = sinhf(fminf(n3, 50.0f)) / n3;
        float f3S = f3 * f3 * S3;
        out[10] = sqrtf(1.0f + f3S);
        for (int i = 1; i < 10; i++) out[10 + i] = f3 * p[i];
    }
}

// ---------------- launch ----------------
extern "C" void kernel_launch(void* const* d_in, const int* in_sizes, int n_in,
                              void* d_out, int out_size){
    const float* x  = (const float*)d_in[0];
    const int*   ei = (const int*)  d_in[1];
    const float* W0 = (const float*)d_in[2];
    const float* b0 = (const float*)d_in[3];
    const float* W1 = (const float*)d_in[4];
    const float* b1 = (const float*)d_in[5];
    const float* W2 = (const float*)d_in[6];
    const float* b2 = (const float*)d_in[7];
    const float* Wc = (const float*)d_in[8];
    const float* bc = (const float*)d_in[9];
    float* out = (float*)d_out;

    uint32_t *pW0h,*pW0l,*pW1h,*pW1l,*pW2h,*pW2l,*pAh,*pV,*pBb;
    float *pbp0,*pbp1,*pbp2;
    cudaGetSymbolAddress((void**)&pW0h, g_W0hi);
    cudaGetSymbolAddress((void**)&pW0l, g_W0lo);
    cudaGetSymbolAddress((void**)&pW1h, g_W1hi);
    cudaGetSymbolAddress((void**)&pW1l, g_W1lo);
    cudaGetSymbolAddress((void**)&pW2h, g_W2hi);
    cudaGetSymbolAddress((void**)&pW2l, g_W2lo);
    cudaGetSymbolAddress((void**)&pbp0, g_bp0);
    cudaGetSymbolAddress((void**)&pbp1, g_bp1);
    cudaGetSymbolAddress((void**)&pbp2, g_bp2);
    cudaGetSymbolAddress((void**)&pAh,  g_Ahi);
    cudaGetSymbolAddress((void**)&pV,   g_v);
    cudaGetSymbolAddress((void**)&pBb,  g_bufBb);

    cudaFuncSetAttribute(mma_gemm<128,128>, cudaFuncAttributeMaxDynamicSharedMemorySize, MMA_SMEM);
    cudaFuncSetAttribute(mma_gemm<128,256>, cudaFuncAttributeMaxDynamicSharedMemorySize, MMA_SMEM);
    cudaFuncSetAttribute(mma_gemm<256,384>, cudaFuncAttributeMaxDynamicSharedMemorySize, MMA_SMEM);

    prep_kernel<128,128><<<(128*64 + 255)/256, 256>>>(W0, b0, pW0h, pW0l, pbp0);
    prep_kernel<256,128><<<(256*64 + 255)/256, 256>>>(W1, b1, pW1h, pW1l, pbp1);
    prep_kernel<384,256><<<(384*128 + 255)/256, 256>>>(W2, b2, pW2h, pW2l, pbp2);

    const int RB = (NNODES + 7) / 8;
    const int NT = (NNODES + 127) / 128;   // 391 row tiles

    lmap0_kernel<<<RB, 256>>>(x);
    scatter_kernel<<<(NEDGES + 15)/16, 256>>>(ei);
    manpre_kernel<<<RB, 256>>>();

    mma_gemm<128,128><<<dim3(1, NT), 256, MMA_SMEM>>>(pAh, pW0h, pW0l, pbp0, pV);
    rowpost_kernel<128><<<RB, 256>>>(pV, pAh);
    mma_gemm<128,256><<<dim3(2, NT), 256, MMA_SMEM>>>(pAh, pW1h, pW1l, pbp1, pV);
    rowpost_kernel<256><<<RB, 256>>>(pV, pAh);
    mma_gemm<256,384><<<dim3(3, NT), 256, MMA_SMEM>>>(pAh, pW2h, pW2l, pbp2, pV);
    rowpost_final_kernel<<<RB, 256>>>(pV, pBb);

    zero384_kernel<<<1, 384>>>();
    mean_kernel<<<200, 192>>>(pBb);
    classify_kernel<<<1, 512>>>(Wc, bc, out);
}

// round 14
// speedup vs baseline: 2.0618x; 1.1742x over previous
#include <cuda_runtime.h>
#include <cuda_fp16.h>
#include <cstdint>

#define NNODES 50000
#define NEDGES 800000
#define EPSF 1e-7f

// ---------------- static device scratch ----------------
__device__ __align__(16) uint32_t g_u0b [NNODES*64];    // u0 packed f16x2 (128 vals)
__device__ __align__(16) uint32_t g_accb[NNODES*64];    // acc packed f16x2
__device__ __align__(16) uint32_t g_v   [NNODES*192];   // GEMM C packed f16x2 (max 384)
__device__ __align__(16) uint32_t g_bufBb[NNODES*192];  // final ht packed f16x2
__device__ __align__(16) uint32_t g_Ahi[NNODES*128];    // A plane f16x2 (max K=256)
__device__ __align__(16) uint32_t g_W0h[128*64];
__device__ __align__(16) uint32_t g_W1h[256*64];
__device__ __align__(16) uint32_t g_W2h[384*128];
__device__ __align__(16) float g_bp0[128];
__device__ __align__(16) float g_bp1[256];
__device__ __align__(16) float g_bp2[384];
__device__ float g_sums[384];

// ---------------- helpers ----------------
__device__ __forceinline__ float warpSum(float v){
#pragma unroll
    for (int o = 16; o > 0; o >>= 1) v += __shfl_xor_sync(0xffffffffu, v, o);
    return v;
}
__device__ __forceinline__ float arcosh_cl(float x){
    x = fmaxf(x, 1.0f + EPSF);
    return logf(x + sqrtf(x * x - 1.0f));
}
__device__ __forceinline__ uint32_t hpack2(float x, float y){
    __half2 h = __floats2half2_rn(x, y);
    return *reinterpret_cast<uint32_t*>(&h);
}
__device__ __forceinline__ void hunpack2(uint32_t p, float& lo, float& hi){
    __half2 h = *reinterpret_cast<__half2*>(&p);
    float2 f = __half22float2(h);
    lo = f.x; hi = f.y;
}
__device__ __forceinline__ void mma_f16(float* c, const uint32_t* a, uint32_t b0, uint32_t b1){
    asm volatile(
        "mma.sync.aligned.m16n8k16.row.col.f32.f16.f16.f32 "
        "{%0,%1,%2,%3}, {%4,%5,%6,%7}, {%8,%9}, {%0,%1,%2,%3};"
        : "+f"(c[0]), "+f"(c[1]), "+f"(c[2]), "+f"(c[3])
        : "r"(a[0]), "r"(a[1]), "r"(a[2]), "r"(a[3]), "r"(b0), "r"(b1));
}
__device__ __forceinline__ void ldmx4(uint32_t& r0, uint32_t& r1, uint32_t& r2, uint32_t& r3,
                                      uint32_t addr){
    asm volatile("ldmatrix.sync.aligned.m8n8.x4.shared.b16 {%0,%1,%2,%3}, [%4];"
                 : "=r"(r0), "=r"(r1), "=r"(r2), "=r"(r3) : "r"(addr));
}
__device__ __forceinline__ uint32_t smem_u32(const void* p){
    return (uint32_t)__cvta_generic_to_shared(p);
}
__device__ __forceinline__ void cp_async16(uint32_t sdst, const void* gsrc, int srcsize){
    asm volatile("cp.async.cg.shared.global [%0], [%1], 16, %2;"
                 :: "r"(sdst), "l"(gsrc), "r"(srcsize) : "memory");
}
#define CP_COMMIT() asm volatile("cp.async.commit_group;" ::: "memory")
#define CP_WAIT(n)  asm volatile("cp.async.wait_group %0;" :: "n"(n) : "memory")

// ---------------- weight padding -> packed fp16 pairs ----------------
template<int MPAD, int KPAD>
__global__ void prep_kernel(const float* __restrict__ W, const float* __restrict__ b,
                            uint32_t* __restrict__ Wh, float* __restrict__ bp){
    int idx = blockIdx.x * blockDim.x + threadIdx.x;
    constexpr int K2 = KPAD / 2;
    if (idx < MPAD * K2){
        int m = idx / K2, kk = idx % K2;
        int k0 = 2 * kk, k1 = 2 * kk + 1;
        float w0 = (m >= 1 && k0 >= 1) ? W[(m - 1) * (KPAD - 1) + (k0 - 1)] : 0.0f;
        float w1 = (m >= 1) ? W[(m - 1) * (KPAD - 1) + (k1 - 1)] : 0.0f;
        Wh[idx] = hpack2(w0, w1);
    }
    if (idx < MPAD) bp[idx] = (idx >= 1) ? b[idx - 1] : 0.0f;
}

// ---------------- log_map_zero(x) -> u0b, accb (packed f16x2) ----------------
__global__ void lmap0_kernel(const float* __restrict__ x){
    int warp = (blockIdx.x * blockDim.x + threadIdx.x) >> 5;
    if (warp >= NNODES) return;
    int lane = threadIdx.x & 31;
    float4 a = ((const float4*)x)[(size_t)warp * 32 + lane];
    float y0 = __shfl_sync(0xffffffffu, a.x, 0);
    float s = a.x*a.x + a.y*a.y + a.z*a.z + a.w*a.w;
    if (lane == 0) s = a.y*a.y + a.z*a.z + a.w*a.w;
    float S = warpSum(s);
    float dist = arcosh_cl(y0 + EPSF);
    float g = dist / sqrtf(S + EPSF);
    float ux = (lane == 0) ? 0.0f : g * a.x;
    uint2 h;
    h.x = hpack2(ux, g * a.y);
    h.y = hpack2(g * a.z, g * a.w);
    ((uint2*)g_u0b )[(size_t)warp * 32 + lane] = h;
    ((uint2*)g_accb)[(size_t)warp * 32 + lane] = h;
}

// ---------------- segment_sum via vector f16x2 red.global (half-warp/edge) ----------------
__global__ void scatter_kernel(const int* __restrict__ ei){
    int e = (blockIdx.x * blockDim.x + threadIdx.x) >> 4;
    if (e >= NEDGES) return;
    int l16 = threadIdx.x & 15;
    int src = ei[e];
    int dst = ei[NEDGES + e];
    uint4 v = ((const uint4*)g_u0b)[(size_t)src * 16 + l16];
    uint32_t* addr = g_accb + (size_t)dst * 64 + l16 * 4;
    asm volatile("red.global.add.noftz.v4.f16x2 [%0], {%1,%2,%3,%4};"
                 :: "l"(addr), "r"(v.x), "r"(v.y), "r"(v.z), "r"(v.w) : "memory");
}

// ---------------- log_map(exp_map(acc)) -> A plane (K=128) ----------------
__global__ void manpre_kernel(){
    int warp = (blockIdx.x * blockDim.x + threadIdx.x) >> 5;
    if (warp >= NNODES) return;
    int lane = threadIdx.x & 31;
    uint2 p = ((const uint2*)g_accb)[(size_t)warp * 32 + lane];
    float ax, ay, az, aw;
    hunpack2(p.x, ax, ay);
    hunpack2(p.y, az, aw);
    float s = ax*ax + ay*ay + az*az + aw*aw;
    float S = warpSum(s);
    float n = sqrtf(fmaxf(S + EPSF, 1e-6f));
    float f = sinhf(fminf(n, 50.0f)) / n;
    float fS = f * f * S;
    float first = sqrtf(1.0f + fS);
    float dist = arcosh_cl(first + EPSF);
    float g = dist / sqrtf(fS + EPSF) * f;
    uint2 h;
    h.x = hpack2(g*ax, g*ay);
    h.y = hpack2(g*az, g*aw);
    ((uint2*)g_Ahi)[(size_t)warp * 32 + lane] = h;
}

// ---------------- post-GEMM chain (f16 in) -> f16 A plane ----------------
template<int MP>
__global__ void rowpost_kernel(const uint32_t* __restrict__ V, uint32_t* __restrict__ Uhi){
    int warp = (blockIdx.x * blockDim.x + threadIdx.x) >> 5;
    if (warp >= NNODES) return;
    int lane = threadIdx.x & 31;
    constexpr int PL = MP / 128;
    const uint2* vr = (const uint2*)(V + (size_t)warp * (MP / 2));
    float a[PL][4];
    float s = 0.0f;
#pragma unroll
    for (int i = 0; i < PL; i++){
        uint2 p = vr[i * 32 + lane];
        hunpack2(p.x, a[i][0], a[i][1]);
        hunpack2(p.y, a[i][2], a[i][3]);
        s += a[i][0]*a[i][0] + a[i][1]*a[i][1] + a[i][2]*a[i][2] + a[i][3]*a[i][3];
    }
    float S = warpSum(s);
    float n = sqrtf(fmaxf(S + EPSF, 1e-6f));
    float f = sinhf(fminf(n, 50.0f)) / n;
    float fS = f * f * S;
    float first = sqrtf(1.0f + fS);
    float dist = arcosh_cl(first + EPSF);
    float g1 = dist / sqrtf(fS + EPSF) * f;
    float s2 = 0.0f;
#pragma unroll
    for (int i = 0; i < PL; i++){
#pragma unroll
        for (int j = 0; j < 4; j++){
            a[i][j] = fmaxf(g1 * a[i][j], 0.0f);
            s2 += a[i][j] * a[i][j];
        }
    }
    float S2 = warpSum(s2);
    float n2 = sqrtf(fmaxf(S2 + EPSF, 1e-6f));
    float f2 = sinhf(fminf(n2, 50.0f)) / n2;
    float f2S = f2 * f2 * S2;
    float first2 = sqrtf(1.0f + f2S);
    float dist2 = arcosh_cl(first2 + EPSF);
    float g2 = dist2 / sqrtf(f2S + EPSF) * f2;
#pragma unroll
    for (int i = 0; i < PL; i++){
        uint2 h;
        h.x = hpack2(g2*a[i][0], g2*a[i][1]);
        h.y = hpack2(g2*a[i][2], g2*a[i][3]);
        ((uint2*)Uhi)[(size_t)warp * (MP / 4) + i * 32 + lane] = h;
    }
}

// ---------------- final rowpost (MP=384, f16 in) -> packed f16 ht ----------------
__global__ void rowpost_final_kernel(const uint32_t* __restrict__ V, uint32_t* __restrict__ Ub){
    int warp = (blockIdx.x * blockDim.x + threadIdx.x) >> 5;
    if (warp >= NNODES) return;
    int lane = threadIdx.x & 31;
    const uint2* vr = (const uint2*)(V + (size_t)warp * 192);
    float a[3][4];
    float s = 0.0f;
#pragma unroll
    for (int i = 0; i < 3; i++){
        uint2 p = vr[i * 32 + lane];
        hunpack2(p.x, a[i][0], a[i][1]);
        hunpack2(p.y, a[i][2], a[i][3]);
        s += a[i][0]*a[i][0] + a[i][1]*a[i][1] + a[i][2]*a[i][2] + a[i][3]*a[i][3];
    }
    float S = warpSum(s);
    float n = sqrtf(fmaxf(S + EPSF, 1e-6f));
    float f = sinhf(fminf(n, 50.0f)) / n;
    float fS = f * f * S;
    float first = sqrtf(1.0f + fS);
    float dist = arcosh_cl(first + EPSF);
    float g1 = dist / sqrtf(fS + EPSF) * f;
    float s2 = 0.0f;
#pragma unroll
    for (int i = 0; i < 3; i++){
#pragma unroll
        for (int j = 0; j < 4; j++){
            a[i][j] = fmaxf(g1 * a[i][j], 0.0f);
            s2 += a[i][j] * a[i][j];
        }
    }
    float S2 = warpSum(s2);
    float n2 = sqrtf(fmaxf(S2 + EPSF, 1e-6f));
    float f2 = sinhf(fminf(n2, 50.0f)) / n2;
    float f2S = f2 * f2 * S2;
    float first2 = sqrtf(1.0f + f2S);
    float dist2 = arcosh_cl(first2 + EPSF);
    float g2 = dist2 / sqrtf(f2S + EPSF) * f2;
#pragma unroll
    for (int i = 0; i < 3; i++){
        uint2 h;
        h.x = hpack2(g2*a[i][0], g2*a[i][1]);
        h.y = hpack2(g2*a[i][2], g2*a[i][3]);
        ((uint2*)Ub)[(size_t)warp * 96 + i * 32 + lane] = h;
    }
}

// ---------------- cp.async double-buffered fp16 single-MMA GEMM with ldmatrix ----------------
// A fp16, W fp16. C = A.W^T + bias, stored packed f16x2.
#define ST2 20
static constexpr int STG_U32 = 2 * 128 * ST2;          // A, W tiles
static constexpr int MMA_SMEM = 2 * STG_U32 * 4;       // 40960 B

template<int K, int MOUT>
__global__ void __launch_bounds__(256, 2) mma_gemm(
        const uint32_t* __restrict__ Ahi, const uint32_t* __restrict__ Wh,
        const float* __restrict__ bias, uint32_t* __restrict__ C){
    extern __shared__ uint32_t smu[];
    int tid = threadIdx.x, lane = tid & 31, wid = tid >> 5;
    int brow = blockIdx.y * 128, bcol = blockIdx.x * 128;
    int mw = wid & 1, nw = wid >> 1;
    int gid = lane >> 2, tig = lane & 3;
    constexpr int NC = K / 32;
    constexpr int K2 = K / 2;

    auto load_stage = [&](int s, int kc){
        uint32_t* base = smu + s * STG_U32;
        uint32_t sAh = smem_u32(base);
        uint32_t sWh = smem_u32(base + 128 * ST2);
        int k0 = kc * 16;
#pragma unroll
        for (int i = 0; i < 2; i++){
            int idx = tid + i * 256;
            int r = idx >> 2;
            int c4 = (idx & 3) << 2;
            uint32_t soff = (uint32_t)(r * ST2 + c4) * 4u;
            int gr = brow + r;
            cp_async16(sAh + soff, Ahi + (size_t)gr * K2 + k0 + c4, (gr < NNODES) ? 16 : 0);
            cp_async16(sWh + soff, Wh + (size_t)(bcol + r) * K2 + k0 + c4, 16);
        }
        CP_COMMIT();
    };

    uint32_t a_off = (uint32_t)((mw * 64 + (lane & 15)) * ST2 + (lane >> 4) * 4) * 4u;
    int wsn = (lane >> 4) & 1;
    int wkh = (lane >> 3) & 1;
    uint32_t w_off[2];
#pragma unroll
    for (int p = 0; p < 2; p++)
        w_off[p] = (uint32_t)((nw * 32 + p * 16 + wsn * 8 + (lane & 7)) * ST2 + wkh * 4) * 4u;

    float acc[4][4][4];
#pragma unroll
    for (int i = 0; i < 4; i++)
#pragma unroll
        for (int j = 0; j < 4; j++)
#pragma unroll
            for (int l = 0; l < 4; l++) acc[i][j][l] = 0.0f;

    load_stage(0, 0);
    if (NC > 1) load_stage(1, 1);

    uint32_t sbase = smem_u32(smu);

    for (int kc = 0; kc < NC; kc++){
        int buf = kc & 1;
        if (kc + 1 < NC) { CP_WAIT(1); } else { CP_WAIT(0); }
        __syncthreads();
        uint32_t sAh = sbase + (uint32_t)(buf * STG_U32) * 4u;
        uint32_t sWh = sAh + 128 * ST2 * 4u;
#pragma unroll
        for (int ks = 0; ks < 2; ks++){
            uint32_t kbb = (uint32_t)(ks * 8) * 4u;
            uint32_t ah[4][4];
#pragma unroll
            for (int sm2 = 0; sm2 < 4; sm2++)
                ldmx4(ah[sm2][0], ah[sm2][1], ah[sm2][2], ah[sm2][3],
                      sAh + a_off + (uint32_t)(sm2 * 16 * ST2) * 4u + kbb);
            uint32_t bh0[4], bh1[4];
#pragma unroll
            for (int p = 0; p < 2; p++)
                ldmx4(bh0[2*p], bh1[2*p], bh0[2*p+1], bh1[2*p+1], sWh + w_off[p] + kbb);
#pragma unroll
            for (int sn = 0; sn < 4; sn++){
#pragma unroll
                for (int sm2 = 0; sm2 < 4; sm2++)
                    mma_f16(acc[sm2][sn], ah[sm2], bh0[sn], bh1[sn]);
            }
        }
        __syncthreads();
        if (kc + 2 < NC) load_stage(buf, kc + 2);
    }

#pragma unroll
    for (int sm2 = 0; sm2 < 4; sm2++){
#pragma unroll
        for (int sn = 0; sn < 4; sn++){
            int row = brow + mw * 64 + sm2 * 16 + gid;
            int col = bcol + nw * 32 + sn * 8 + tig * 2;
            float2 bb = *(const float2*)(bias + col);
            if (row < NNODES){
                C[(size_t)row * (MOUT/2) + (col >> 1)] =
                    hpack2(acc[sm2][sn][0] + bb.x, acc[sm2][sn][1] + bb.y);
            }
            if (row + 8 < NNODES){
                C[(size_t)(row + 8) * (MOUT/2) + (col >> 1)] =
                    hpack2(acc[sm2][sn][2] + bb.x, acc[sm2][sn][3] + bb.y);
            }
        }
    }
}

// ---------------- mean over nodes (f16 in, fp32 sums) ----------------
__global__ void zero384_kernel(){ g_sums[threadIdx.x] = 0.0f; }

__global__ void mean_kernel(const uint32_t* __restrict__ U){
    int t = threadIdx.x;              // 192 threads, one u32 column each
    int start = blockIdx.x * 250;
    int end = start + 250;
    float s0 = 0.0f, s1 = 0.0f;
    for (int nn = start; nn < end; nn++){
        uint32_t p = U[(size_t)nn * 192 + t];
        float lo, hi;
        hunpack2(p, lo, hi);
        s0 += lo; s1 += hi;
    }
    atomicAdd(&g_sums[2 * t],     s0);
    atomicAdd(&g_sums[2 * t + 1], s1);
}

// ---------------- final classifier head ----------------
__global__ void classify_kernel(const float* __restrict__ Wc, const float* __restrict__ bc,
                                float* __restrict__ out){
    __shared__ float sh_hm[384];
    __shared__ float sh_warp[16];
    __shared__ float sh_mx[10];
    __shared__ float sh_factor;
    int t = threadIdx.x, lane = t & 31, wid = t >> 5;
    float v = 0.0f;
    if (t < 384) v = g_sums[t] * (1.0f / (float)NNODES);
    if (t == 0) v = 0.0f;
    if (t < 384) sh_hm[t] = v;
    float s = warpSum(v * v);
    if (lane == 0) sh_warp[wid] = s;
    __syncthreads();
    if (t == 0){
        float S = 0.0f;
        for (int i = 0; i < 16; i++) S += sh_warp[i];
        float nrm = sqrtf(S + EPSF);
        float dist = arcosh_cl(0.0f + EPSF);
        sh_factor = dist / nrm;
    }
    __syncthreads();
    float factor = sh_factor;
    if (wid < 9){
        float d = 0.0f;
        for (int j = lane; j < 383; j += 32) d += sh_hm[j + 1] * factor * Wc[wid * 383 + j];
        d = warpSum(d);
        if (lane == 0) sh_mx[wid + 1] = d + bc[wid];
    }
    if (t == 0) sh_mx[0] = 0.0f;
    __syncthreads();
    if (t == 0){
        float mx[10];
#pragma unroll
        for (int i = 0; i < 10; i++) mx[i] = sh_mx[i];
        float S = 0.0f;
        for (int i = 1; i < 10; i++) S += mx[i] * mx[i];
        float n = sqrtf(fmaxf(S + EPSF, 1e-6f));
        float f = sinhf(fminf(n, 50.0f)) / n;
        float fS = f * f * S;
        float hc[10];
        bool cond = (S == 0.0f);
        if (cond){
            for (int i = 0; i < 10; i++) hc[i] = 0.0f;
        } else {
            hc[0] = sqrtf(1.0f + fS);
            for (int i = 1; i < 10; i++) hc[i] = f * mx[i];
        }
        for (int i = 0; i < 10; i++) out[i] = hc[i];
        float x0c = fmaxf(hc[0] + EPSF, 1.0f + EPSF);
        float dd = logf(x0c + sqrtf(x0c * x0c - 1.0f));
        float tn = 0.0f;
        for (int i = 1; i < 10; i++) tn += hc[i] * hc[i];
        float nr = sqrtf(tn + EPSF);
        float gf = dd / nr;
        float lt[10]; lt[0] = 0.0f;
        for (int i = 1; i < 10; i++) lt[i] = gf * hc[i];
        float mmax = lt[0];
        for (int i = 1; i < 10; i++) mmax = fmaxf(mmax, lt[i]);
        float e[10], se = 0.0f;
        for (int i = 0; i < 10; i++){ e[i] = expf(lt[i] - mmax); se += e[i]; }
        float p[10];
        for (int i = 0; i < 10; i++) p[i] = e[i] / se;
        p[0] = 0.0f;
        float S3 = 0.0f;
        for (int i = 1; i < 10; i++) S3 += p[i] * p[i];
        float n3 = sqrtf(fmaxf(S3 + EPSF, 1e-6f));
        float f3 = sinhf(fminf(n3, 50.0f)) / n3;
        float f3S = f3 * f3 * S3;
        out[10] = sqrtf(1.0f + f3S);
        for (int i = 1; i < 10; i++) out[10 + i] = f3 * p[i];
    }
}

// ---------------- launch ----------------
extern "C" void kernel_launch(void* const* d_in, const int* in_sizes, int n_in,
                              void* d_out, int out_size){
    const float* x  = (const float*)d_in[0];
    const int*   ei = (const int*)  d_in[1];
    const float* W0 = (const float*)d_in[2];
    const float* b0 = (const float*)d_in[3];
    const float* W1 = (const float*)d_in[4];
    const float* b1 = (const float*)d_in[5];
    const float* W2 = (const float*)d_in[6];
    const float* b2 = (const float*)d_in[7];
    const float* Wc = (const float*)d_in[8];
    const float* bc = (const float*)d_in[9];
    float* out = (float*)d_out;

    uint32_t *pW0h,*pW1h,*pW2h,*pAh,*pV,*pBb;
    float *pbp0,*pbp1,*pbp2;
    cudaGetSymbolAddress((void**)&pW0h, g_W0h);
    cudaGetSymbolAddress((void**)&pW1h, g_W1h);
    cudaGetSymbolAddress((void**)&pW2h, g_W2h);
    cudaGetSymbolAddress((void**)&pbp0, g_bp0);
    cudaGetSymbolAddress((void**)&pbp1, g_bp1);
    cudaGetSymbolAddress((void**)&pbp2, g_bp2);
    cudaGetSymbolAddress((void**)&pAh,  g_Ahi);
    cudaGetSymbolAddress((void**)&pV,   g_v);
    cudaGetSymbolAddress((void**)&pBb,  g_bufBb);

    cudaFuncSetAttribute(mma_gemm<128,128>, cudaFuncAttributeMaxDynamicSharedMemorySize, MMA_SMEM);
    cudaFuncSetAttribute(mma_gemm<128,256>, cudaFuncAttributeMaxDynamicSharedMemorySize, MMA_SMEM);
    cudaFuncSetAttribute(mma_gemm<256,384>, cudaFuncAttributeMaxDynamicSharedMemorySize, MMA_SMEM);

    prep_kernel<128,128><<<(128*64 + 255)/256, 256>>>(W0, b0, pW0h, pbp0);
    prep_kernel<256,128><<<(256*64 + 255)/256, 256>>>(W1, b1, pW1h, pbp1);
    prep_kernel<384,256><<<(384*128 + 255)/256, 256>>>(W2, b2, pW2h, pbp2);

    const int RB = (NNODES + 7) / 8;
    const int NT = (NNODES + 127) / 128;   // 391 row tiles

    lmap0_kernel<<<RB, 256>>>(x);
    scatter_kernel<<<(NEDGES + 15)/16, 256>>>(ei);
    manpre_kernel<<<RB, 256>>>();

    mma_gemm<128,128><<<dim3(1, NT), 256, MMA_SMEM>>>(pAh, pW0h, pbp0, pV);
    rowpost_kernel<128><<<RB, 256>>>(pV, pAh);
    mma_gemm<128,256><<<dim3(2, NT), 256, MMA_SMEM>>>(pAh, pW1h, pbp1, pV);
    rowpost_kernel<256><<<RB, 256>>>(pV, pAh);
    mma_gemm<256,384><<<dim3(3, NT), 256, MMA_SMEM>>>(pAh, pW2h, pbp2, pV);
    rowpost_final_kernel<<<RB, 256>>>(pV, pBb);

    zero384_kernel<<<1, 384>>>();
    mean_kernel<<<200, 192>>>(pBb);
    classify_kernel<<<1, 512>>>(Wc, bc, out);
}